// round 12
// baseline (speedup 1.0000x reference)
#include <cuda_runtime.h>
#include <cuda_bf16.h>
#include <math.h>
#include <stdint.h>

// ---------------- problem dims ----------------
constexpr int BSZ = 16;
constexpr int SEQ = 1024;
constexpr int DM  = 512;
constexpr int NG  = 4;
constexpr int CG  = 128;
constexpr int NH  = 8;
constexpr int CH  = 64;
constexpr int NP  = 127;
constexpr int PL  = 16;
constexpr int P2  = NP * PL;   // 2032
constexpr int KP2 = P2 / 2;    // 1016

// ---------------- scratch ----------------
__device__ float g_xn [(size_t)BSZ*SEQ*DM];
__device__ float g_Z  [(size_t)BSZ*SEQ*12];
__device__ float g_w1 [BSZ*NG*SEQ];
__device__ float g_U   [DM*12];
__device__ float g_Weff[3*CG];
__device__ float g_beff[1];
__device__ float g_cB  [12];
__device__ float g_cat0[80*DM];
__device__ float g_sclq[80];
__device__ float g_qcat[80*DM];
__device__ float g_cat1[81*DM];
__device__ float g_cat2[82*DM];
__device__ float g_scl2[82];
__device__ float g_cat3[82*DM];
__device__ float g_Kg2[BSZ*NG*DM];
__device__ float g_Vg2[BSZ*NG*DM];
__device__ uint32_t g_wtH[(size_t)KP2*SEQ];
__device__ uint32_t g_wtL[(size_t)KP2*SEQ];
__device__ uint32_t g_ytH[(size_t)BSZ*KP2*DM];
__device__ uint32_t g_ytL[(size_t)BSZ*KP2*DM];
__device__ uint32_t g_x2dH[(size_t)(DM/2)*BSZ*SEQ];
__device__ uint32_t g_x2dL[(size_t)(DM/2)*BSZ*SEQ];
__device__ uint32_t g_pbH[(DM/2)*DM];
__device__ uint32_t g_pbL[(DM/2)*DM];

__device__ __forceinline__ float warp_sum(float v) {
  #pragma unroll
  for (int o = 16; o; o >>= 1) v += __shfl_xor_sync(0xffffffffu, v, o);
  return v;
}
__device__ __forceinline__ void split_bf16(float v, uint32_t& hb, uint32_t& lb) {
  __nv_bfloat16 h = __float2bfloat16(v);
  float hf = __bfloat162float(h);
  __nv_bfloat16 l = __float2bfloat16(v - hf);
  hb = (uint32_t)__bfloat16_as_ushort(h);
  lb = (uint32_t)__bfloat16_as_ushort(l);
}
__device__ __forceinline__ void pack_pair(float v0, float v1, uint32_t& hw, uint32_t& lw) {
  uint32_t h0, l0, h1, l1;
  split_bf16(v0, h0, l0);
  split_bf16(v1, h1, l1);
  hw = h0 | (h1 << 16);
  lw = l0 | (l1 << 16);
}
__device__ __forceinline__ void mma_bf16(float* c,
    uint32_t a0, uint32_t a1, uint32_t a2, uint32_t a3,
    uint32_t b0, uint32_t b1) {
  asm volatile(
    "mma.sync.aligned.m16n8k16.row.col.f32.bf16.bf16.f32 "
    "{%0,%1,%2,%3}, {%4,%5,%6,%7}, {%8,%9}, {%0,%1,%2,%3};"
    : "+f"(c[0]), "+f"(c[1]), "+f"(c[2]), "+f"(c[3])
    : "r"(a0), "r"(a1), "r"(a2), "r"(a3), "r"(b0), "r"(b1));
}
__device__ __forceinline__ uint32_t smem_u32(const void* p) {
  uint32_t a;
  asm("{ .reg .u64 t; cvta.to.shared.u64 t, %1; cvt.u32.u64 %0, t; }" : "=r"(a) : "l"(p));
  return a;
}
__device__ __forceinline__ void cp_async16(uint32_t s, const void* g) {
  asm volatile("cp.async.cg.shared.global [%0], [%1], 16;" :: "r"(s), "l"(g));
}

// ---------------- Weff ----------------
__global__ void weff_kernel(const float* __restrict__ off1_w,
                            const float* __restrict__ off2_w,
                            float* __restrict__ Weff) {
  int outi = blockIdx.x;
  int t = threadIdx.x; // 128
  __shared__ float red[4];
  float p = off1_w[(long)outi * CG + t] * off2_w[t];
  p = warp_sum(p);
  if ((t & 31) == 0) red[t >> 5] = p;
  __syncthreads();
  if (t == 0) Weff[outi] = red[0] + red[1] + red[2] + red[3];
}

// ---------------- U: warp per d ----------------
__global__ void u_kernel(const float* __restrict__ wq, const float* __restrict__ Weff,
                         float* __restrict__ U) {
  int tid = threadIdx.x; // 256
  int warp = tid >> 5, lane = tid & 31;
  int d = blockIdx.x * 8 + warp;
  float wqv[16], we[12];
  #pragma unroll
  for (int g = 0; g < 4; g++)
    #pragma unroll
    for (int k = 0; k < 4; k++)
      wqv[g * 4 + k] = wq[d * DM + g * CG + k * 32 + lane];
  #pragma unroll
  for (int w = 0; w < 3; w++)
    #pragma unroll
    for (int k = 0; k < 4; k++)
      we[w * 4 + k] = Weff[w * CG + k * 32 + lane];
  #pragma unroll
  for (int w = 0; w < 3; w++) {
    #pragma unroll
    for (int g = 0; g < 4; g++) {
      float s = 0.f;
      #pragma unroll
      for (int k = 0; k < 4; k++) s += wqv[g * 4 + k] * we[w * 4 + k];
      s = warp_sum(s);
      if (lane == 0) U[d * 12 + w * 4 + g] = s;
    }
  }
}

// ---------------- fused LayerNorm + Z: warp-per-row, U staged in smem ------
__global__ void ln_z_kernel(const float* __restrict__ x,
                            const float* __restrict__ lw,
                            const float* __restrict__ lb,
                            const float* __restrict__ U,
                            float* __restrict__ xn, float* __restrict__ Z) {
  __shared__ float Us[DM * 13];
  int tid = threadIdx.x; // 256
  for (int idx = tid; idx < DM * 12; idx += 256) {
    int d = idx / 12, j = idx - d * 12;
    Us[d * 13 + j] = U[idx];
  }
  __syncthreads();
  int warp = tid >> 5, lane = tid & 31;
  long row = (long)blockIdx.x * 8 + warp;
  const float* xr = x + row * DM;
  float* o = xn + row * DM;
  float v[16];
  float s = 0.f;
  #pragma unroll
  for (int k = 0; k < 16; k++) {
    v[k] = xr[k * 32 + lane];
    s += v[k];
  }
  s = warp_sum(s);
  float mu = s * (1.0f / 512.0f);
  float sq = 0.f;
  #pragma unroll
  for (int k = 0; k < 16; k++) {
    float d = v[k] - mu;
    sq += d * d;
  }
  sq = warp_sum(sq);
  float inv = rsqrtf(sq * (1.0f / 512.0f) + 1e-5f);
  float acc[12];
  #pragma unroll
  for (int j = 0; j < 12; j++) acc[j] = 0.f;
  #pragma unroll
  for (int k = 0; k < 16; k++) {
    int d = k * 32 + lane;
    float ov = (v[k] - mu) * inv * lw[d] + lb[d];
    o[d] = ov;
    const float* ur = &Us[d * 13];
    #pragma unroll
    for (int j = 0; j < 12; j++) acc[j] += ov * ur[j];
  }
  #pragma unroll
  for (int j = 0; j < 12; j++) acc[j] = warp_sum(acc[j]);
  if (lane == 0) {
    #pragma unroll
    for (int j = 0; j < 12; j++) Z[row * 12 + j] = acc[j];
  }
}

// ---------------- constants + zero-init ----------------
__global__ void cb_kernel(const float* __restrict__ off1_b,
                          const float* __restrict__ off2_w,
                          const float* __restrict__ bq,
                          const float* __restrict__ bo,
                          const float* __restrict__ Weff,
                          float* __restrict__ beff, float* __restrict__ cB,
                          float* __restrict__ sclq, float* __restrict__ scl2,
                          float* __restrict__ cat0,
                          float* __restrict__ cat1, float* __restrict__ cat2) {
  int t = threadIdx.x; // 128
  if (t < 12) {
    int w = t >> 2, g = t & 3;
    float s = 0.f;
    for (int c = 0; c < CG; c++) s += bq[g * CG + c] * Weff[w * CG + c];
    cB[t] = s;
  } else if (t == 12) {
    float s = 0.f;
    for (int o = 0; o < CG; o++) s += off1_b[o] * off2_w[o];
    *beff = s;
  }
  if (t < 64) sclq[t] = 0.f;
  if (t >= 64 && t < 80) sclq[t] = 1024.f;
  if (t < 82) scl2[t] = (t == 81) ? 1.f : 0.f;
  for (int j = t; j < DM; j += 128) {
    cat1[80 * DM + j] = 1.f;
    cat2[81 * DM + j] = bo[j];
  }
  for (int j = t; j < 80 * DM; j += 128) cat0[j] = 0.f;
}

__global__ void w1_kernel(const float* __restrict__ Z, const float* __restrict__ beff,
                          const float* __restrict__ cB, float* __restrict__ w1) {
  int bg = blockIdx.x;
  int b = bg >> 2, g = bg & 3;
  int l = blockIdx.y * 256 + threadIdx.x;
  float s = *beff;
  #pragma unroll
  for (int w = 0; w < 3; w++) {
    int lw = l + w - 1;
    if (lw >= 0 && lw < SEQ)
      s += Z[((long)b * SEQ + lw) * 12 + w * 4 + g] + cB[w * 4 + g];
  }
  float off = tanhf(s) * 3.0f;
  float ixv = ((float)l + off) * (1.0f / 1023.0f) - 0.5f;
  w1[bg * SEQ + l] = 1.0f - fabsf(ixv);
}

// ---------------- w1x: strip-parallel, atomics ----------------
__global__ void w1x_kernel(const float* __restrict__ xn, const float* __restrict__ w1,
                           float* __restrict__ cat0, float* __restrict__ sclq) {
  int b = blockIdx.x, ec = blockIdx.y, ls = blockIdx.z;
  int e = ec * 128 + threadIdx.x;  // 128 threads
  int lbeg = ls * 256;
  __shared__ float w1s[NG][256];
  int tid = threadIdx.x;
  for (int idx = tid; idx < NG * 256; idx += 128) {
    int g = idx >> 8, l = idx & 255;
    w1s[g][l] = w1[(b * NG + g) * SEQ + lbeg + l];
  }
  __syncthreads();
  float a0 = 0, a1 = 0, a2 = 0, a3 = 0, as_ = 0;
  const float* xb = xn + ((long)b * SEQ + lbeg) * DM + e;
  for (int l = 0; l < 256; l++) {
    float xv = xb[(long)l * DM];
    a0 += xv * w1s[0][l]; a1 += xv * w1s[1][l];
    a2 += xv * w1s[2][l]; a3 += xv * w1s[3][l];
    as_ += xv;
  }
  atomicAdd(&cat0[(b * NG + 0) * DM + e], a0);
  atomicAdd(&cat0[(b * NG + 1) * DM + e], a1);
  atomicAdd(&cat0[(b * NG + 2) * DM + e], a2);
  atomicAdd(&cat0[(b * NG + 3) * DM + e], a3);
  atomicAdd(&cat0[(64 + b) * DM + e], as_);
  if (ec == 0 && tid < 4) {
    float acc = 0.f;
    for (int l = 0; l < 256; l++) acc += w1s[tid][l];
    atomicAdd(&sclq[b * NG + tid], acc);
  }
}

// ---------------- Kg/Vg ----------------
__global__ void kgvg_kernel(const float* __restrict__ xn,
                            const float* __restrict__ wk, const float* __restrict__ wv,
                            float* __restrict__ Kg, float* __restrict__ Vg) {
  int bg = blockIdx.x; int b = bg >> 2, g = bg & 3;
  int e = blockIdx.y * 128 + threadIdx.x;
  __shared__ float ms[CG];
  ms[threadIdx.x] = 0.5f * (xn[((long)b * SEQ + 511) * DM + g * CG + threadIdx.x] +
                            xn[((long)b * SEQ + 512) * DM + g * CG + threadIdx.x]);
  __syncthreads();
  float sk = 0.f, sv = 0.f;
  for (int c = 0; c < CG; c++) {
    float mv = ms[c];
    sk += mv * wk[(g * CG + c) * DM + e];
    sv += mv * wv[(g * CG + c) * DM + e];
  }
  Kg[bg * DM + e] = sk;
  Vg[bg * DM + e] = sv;
}

__global__ void rowgemm2(const float* __restrict__ A, const float* __restrict__ B,
                         float* __restrict__ C, int K, int N,
                         const float* __restrict__ scalev, float cscale,
                         const float* __restrict__ biasv) {
  int r = blockIdx.x;
  int e = blockIdx.y * 128 + threadIdx.x;
  __shared__ float Ar[1024];
  for (int idx = threadIdx.x; idx < K; idx += 128)
    Ar[idx] = A ? A[(long)r * K + idx] : 1.0f;
  __syncthreads();
  float s = 0.f;
  for (int d = 0; d < K; d++) s += Ar[d] * B[(long)d * N + e];
  if (biasv) {
    float sc = scalev ? scalev[r] : cscale;
    s += sc * biasv[e];
  }
  C[(long)r * N + e] = s;
}

__global__ void attn_kernel(const float* __restrict__ qcat,
                            const float* __restrict__ Kg, const float* __restrict__ Vg,
                            const float* __restrict__ bk, const float* __restrict__ bv,
                            float* __restrict__ cat1) {
  int b = blockIdx.x, h = blockIdx.y;
  int i = threadIdx.x; // 64
  __shared__ float Kgs[NG][CH], Vgs[NG][CH], bks[CH], bvs[CH];
  __shared__ float aa[CH][CH + 1];
  #pragma unroll
  for (int g = 0; g < NG; g++) {
    Kgs[g][i] = Kg[(b * NG + g) * DM + h * CH + i];
    Vgs[g][i] = Vg[(b * NG + g) * DM + h * CH + i];
  }
  bks[i] = bk[h * CH + i];
  bvs[i] = bv[h * CH + i];
  __syncthreads();
  float qw0 = qcat[(b * NG + 0) * DM + h * CH + i];
  float qw1 = qcat[(b * NG + 1) * DM + h * CH + i];
  float qw2 = qcat[(b * NG + 2) * DM + h * CH + i];
  float qw3 = qcat[(b * NG + 3) * DM + h * CH + i];
  float qsv = qcat[(64 + b) * DM + h * CH + i];
  const float scale = 0.044194173824159216f;
  float mx = -1e30f;
  for (int j = 0; j < CH; j++) {
    float s = (qw0 * Kgs[0][j] + qw1 * Kgs[1][j] + qw2 * Kgs[2][j] + qw3 * Kgs[3][j]
               + qsv * bks[j]) * scale;
    aa[i][j] = s;
    mx = fmaxf(mx, s);
  }
  float sm = 0.f;
  for (int j = 0; j < CH; j++) { float e = expf(aa[i][j] - mx); aa[i][j] = e; sm += e; }
  float inv = 1.0f / sm;
  float ag0 = 0, ag1 = 0, ag2 = 0, ag3 = 0, ab = 0;
  for (int j = 0; j < CH; j++) {
    float w = aa[i][j] * inv;
    ag0 += w * Vgs[0][j]; ag1 += w * Vgs[1][j];
    ag2 += w * Vgs[2][j]; ag3 += w * Vgs[3][j];
    ab  += w * bvs[j];
  }
  cat1[(b * NG + 0) * DM + h * CH + i] = ag0;
  cat1[(b * NG + 1) * DM + h * CH + i] = ag1;
  cat1[(b * NG + 2) * DM + h * CH + i] = ag2;
  cat1[(b * NG + 3) * DM + h * CH + i] = ag3;
  cat1[(64 + b) * DM + h * CH + i] = ab;
}

// ---------------- per-patch 2D deformable attention (512 threads) ---------
constexpr int PDW = DM + 4;
struct PatchSmem {
  float P[PL][PDW];
  float XS[PL][PDW];
  float sc[PL][PL + 1];
  float attnb[PL];
  float rsP[PL];
  float rsX[PL];
  float red[2][PL][PL];
};

__global__ void patch_kernel(const float* __restrict__ xn,
                             uint32_t* __restrict__ ytH, uint32_t* __restrict__ ytL,
                             const float* __restrict__ offc1w, const float* __restrict__ offc1b,
                             const float* __restrict__ offc2w,
                             const float* __restrict__ wq2, const float* __restrict__ bq2,
                             const float* __restrict__ wk2, const float* __restrict__ bk2,
                             const float* __restrict__ wv2, const float* __restrict__ bv2,
                             const float* __restrict__ wo2, const float* __restrict__ bo2,
                             const float* __restrict__ bias2d) {
  extern __shared__ char smraw[];
  PatchSmem& S = *(PatchSmem*)smraw;
  int pb = blockIdx.x;
  int b = pb / NP, p = pb % NP;
  int tid = threadIdx.x; // 512
  const float* src = xn + ((long)b * SEQ + p * 8) * DM;
  for (int idx = tid; idx < PL * DM / 4; idx += 512) {
    int i = idx >> 7, j4 = (idx & 127) * 4;
    *(float4*)&S.P[i][j4] = *(const float4*)(src + i * DM + j4);
  }
  __syncthreads();

  float WQ2 = *wq2, BQ2 = *bq2;
  float cw[9];
  #pragma unroll
  for (int t = 0; t < 9; t++) cw[t] = offc1w[t];
  float c1b = *offc1b;
  float ow0 = offc2w[0], ow1 = offc2w[1];

  for (int idx = tid; idx < PL * DM; idx += 512) {
    int i = idx >> 9, j = idx & 511;
    float h2 = c1b;
    #pragma unroll
    for (int di = -1; di <= 1; di++) {
      int ii = i + di;
      if (ii < 0 || ii > PL - 1) continue;
      #pragma unroll
      for (int dj = -1; dj <= 1; dj++) {
        int jj = j + dj;
        if (jj < 0 || jj > DM - 1) continue;
        h2 += (WQ2 * S.P[ii][jj] + BQ2) * cw[(di + 1) * 3 + (dj + 1)];
      }
    }
    float ox = tanhf(h2 * ow0) * 3.0f;
    float oy = tanhf(h2 * ow1) * 3.0f;
    float ix = ((float)j + ox) * (512.0f / 511.0f) - 0.5f;
    float iy = ((float)i + oy) * (16.0f / 15.0f) - 0.5f;
    float x0f = floorf(ix), y0f = floorf(iy);
    int x0 = (int)x0f, y0 = (int)y0f;
    float wx = ix - x0f, wy = iy - y0f;
    float acc = 0.f;
    if (x0 >= 0 && x0 < DM && y0 >= 0 && y0 < PL)                 acc += S.P[y0][x0]         * (1 - wx) * (1 - wy);
    if (x0 + 1 >= 0 && x0 + 1 < DM && y0 >= 0 && y0 < PL)         acc += S.P[y0][x0 + 1]     * wx * (1 - wy);
    if (x0 >= 0 && x0 < DM && y0 + 1 >= 0 && y0 + 1 < PL)         acc += S.P[y0 + 1][x0]     * (1 - wx) * wy;
    if (x0 + 1 >= 0 && x0 + 1 < DM && y0 + 1 >= 0 && y0 + 1 < PL) acc += S.P[y0 + 1][x0 + 1] * wx * wy;
    S.XS[i][j] = acc;
  }
  __syncthreads();

  if (tid < 256) {
    int i = tid >> 4, seg = tid & 15;
    float sp = 0.f, sx = 0.f;
    int w0 = seg * 32;
    for (int w = w0; w < w0 + 32; w++) { sp += S.P[i][w]; sx += S.XS[i][w]; }
    S.red[0][i][seg] = sp;
    S.red[1][i][seg] = sx;
  }
  __syncthreads();
  if (tid < 2 * PL) {
    int arr = tid >> 4, i = tid & 15;
    float s = 0.f;
    #pragma unroll
    for (int seg = 0; seg < 16; seg++) s += S.red[arr][i][seg];
    if (arr == 0) S.rsP[i] = s; else S.rsX[i] = s;
  }
  __syncthreads();

  if (tid < 256) {
    float WK2 = *wk2, BK2 = *bk2;
    float s1 = WQ2 * WK2, s2 = WQ2 * BK2, s3 = BQ2 * WK2, s4 = 512.0f * BQ2 * BK2;
    int i = tid >> 4, jj = tid & 15;
    const float4* pr = (const float4*)S.P[i];
    const float4* xr = (const float4*)S.XS[jj];
    float dx = 0.f, dy = 0.f, dz = 0.f, dw = 0.f;
    #pragma unroll 4
    for (int w4 = 0; w4 < 128; w4++) {
      float4 a = pr[w4], c = xr[w4];
      dx += a.x * c.x; dy += a.y * c.y; dz += a.z * c.z; dw += a.w * c.w;
    }
    float dot = (dx + dy) + (dz + dw);
    S.sc[i][jj] = s1 * dot + s2 * S.rsP[i] + s3 * S.rsX[jj] + s4;
  }
  __syncthreads();
  if (tid < PL) {
    int i = tid;
    float mx = -1e30f;
    for (int jj = 0; jj < PL; jj++) mx = fmaxf(mx, S.sc[i][jj]);
    float sm = 0.f;
    for (int jj = 0; jj < PL; jj++) { float e = expf(S.sc[i][jj] - mx); S.sc[i][jj] = e; sm += e; }
    float inv = 1.0f / sm;
    float ab = 0.f;
    for (int jj = 0; jj < PL; jj++) { S.sc[i][jj] *= inv; ab += S.sc[i][jj] * bias2d[jj]; }
    S.attnb[i] = ab;
  }
  __syncthreads();

  float WV2 = *wv2, BV2 = *bv2, WO2 = *wo2, BO2 = *bo2;
  for (int idx = tid; idx < 8 * 128; idx += 512) {
    int i2 = (idx >> 7) * 2;
    int w4 = (idx & 127) * 4;
    float4 s0 = {0, 0, 0, 0}, s1 = {0, 0, 0, 0};
    #pragma unroll
    for (int jj = 0; jj < PL; jj++) {
      float a0 = S.sc[i2][jj], a1 = S.sc[i2 + 1][jj];
      float4 xv = *(const float4*)&S.XS[jj][w4];
      s0.x += a0 * xv.x; s0.y += a0 * xv.y; s0.z += a0 * xv.z; s0.w += a0 * xv.w;
      s1.x += a1 * xv.x; s1.y += a1 * xv.y; s1.z += a1 * xv.z; s1.w += a1 * xv.w;
    }
    float c0 = BV2 + S.attnb[i2], c1 = BV2 + S.attnb[i2 + 1];
    float o0x = (WV2 * s0.x + c0) * WO2 + BO2, o1x = (WV2 * s1.x + c1) * WO2 + BO2;
    float o0y = (WV2 * s0.y + c0) * WO2 + BO2, o1y = (WV2 * s1.y + c1) * WO2 + BO2;
    float o0z = (WV2 * s0.z + c0) * WO2 + BO2, o1z = (WV2 * s1.z + c1) * WO2 + BO2;
    float o0w = (WV2 * s0.w + c0) * WO2 + BO2, o1w = (WV2 * s1.w + c1) * WO2 + BO2;
    uint4 hv, lv;
    pack_pair(o0x, o1x, hv.x, lv.x);
    pack_pair(o0y, o1y, hv.y, lv.y);
    pack_pair(o0z, o1z, hv.z, lv.z);
    pack_pair(o0w, o1w, hv.w, lv.w);
    long kp = (long)b * KP2 + p * 8 + (i2 >> 1);
    *(uint4*)&ytH[kp * DM + w4] = hv;
    *(uint4*)&ytL[kp * DM + w4] = lv;
  }
}

// ---------------- convert float [K][N] -> packed bf16-pair H/L [K/2][N] ----
__global__ void convPair_kernel(const float* __restrict__ src,
                                uint32_t* __restrict__ dH, uint32_t* __restrict__ dL,
                                int N, int logN) {
  long idx = (long)blockIdx.x * 256 + threadIdx.x;
  int n = (int)(idx & (N - 1));
  long kp = idx >> logN;
  float v0 = src[(2 * kp) * N + n];
  float v1 = src[(2 * kp + 1) * N + n];
  uint32_t hw, lw;
  pack_pair(v0, v1, hw, lw);
  dH[idx] = hw;
  dL[idx] = lw;
}

// ============================================================================
// bf16x3 mma.sync GEMM (R8-proven): 128x128 tile, 2 CTAs/SM, 3-stage cp.async.
// ============================================================================
constexpr int MLDP = 136;
constexpr int TSZP = 8 * MLDP;
constexpr int G_SMEM_WORDS = 3 * 4 * TSZP + 11 * 128;
constexpr int G_SMEM_BYTES = G_SMEM_WORDS * 4;

template<int EPI>
__global__ __launch_bounds__(256, 2)
void mma_gemm2(const uint32_t* __restrict__ AHg, const uint32_t* __restrict__ ALg, int lda,
               const uint32_t* __restrict__ BHg, const uint32_t* __restrict__ BLg, int ldb,
               long long sB, int N, int K,
               const float* __restrict__ biasM,
               float* __restrict__ Cf,
               uint32_t* __restrict__ CH, uint32_t* __restrict__ CL, int ldc, int zMul,
               const float* __restrict__ w1, const float* __restrict__ cat3,
               const float* __restrict__ bias1d) {
  extern __shared__ uint32_t smu[];
  float* Ep = (float*)(smu + 12 * TSZP);
  float* Rp = Ep + 6 * 128;

  BHg += blockIdx.z * sB;
  BLg += blockIdx.z * sB;
  const int m0 = blockIdx.y * 128, n0 = blockIdx.x * 128;
  const int tid = threadIdx.x;
  const int wid = tid >> 5, lane = tid & 31;
  const int wm = wid >> 2, wn = wid & 3;
  const int grp = lane >> 2, tig = lane & 3;
  const uint32_t smb = smem_u32(smu);

  if (EPI == 1 && tid < 128) {
    int bb = (int)(blockIdx.y >> 3);
    int n = n0 + tid;
    Ep[0 * 128 + tid] = cat3[(64 + bb) * 512 + n] + cat3[81 * 512 + n];
    Ep[1 * 128 + tid] = cat3[80 * 512 + n];
    Ep[2 * 128 + tid] = cat3[(bb * 4 + 0) * 512 + n];
    Ep[3 * 128 + tid] = cat3[(bb * 4 + 1) * 512 + n];
    Ep[4 * 128 + tid] = cat3[(bb * 4 + 2) * 512 + n];
    Ep[5 * 128 + tid] = cat3[(bb * 4 + 3) * 512 + n];
    int l = (m0 & 1023) + tid;
    Rp[0 * 128 + tid] = w1[(bb * 4 + 0) * 1024 + l];
    Rp[1 * 128 + tid] = w1[(bb * 4 + 1) * 1024 + l];
    Rp[2 * 128 + tid] = w1[(bb * 4 + 2) * 1024 + l];
    Rp[3 * 128 + tid] = w1[(bb * 4 + 3) * 1024 + l];
    Rp[4 * 128 + tid] = bias1d[l];
  }

  const int r = tid >> 5;
  const int cc = (tid & 31) * 4;
  auto issue_stage = [&](int kt, int buf) {
    long kp0 = (long)kt * 8 + r;
    uint32_t sd = smb + (uint32_t)(buf * 4 * TSZP + r * MLDP + cc) * 4;
    cp_async16(sd,                AHg + kp0 * lda + m0 + cc);
    cp_async16(sd + TSZP * 4,     ALg + kp0 * lda + m0 + cc);
    cp_async16(sd + 2 * TSZP * 4, BHg + kp0 * ldb + n0 + cc);
    cp_async16(sd + 3 * TSZP * 4, BLg + kp0 * ldb + n0 + cc);
    asm volatile("cp.async.commit_group;");
  };

  float c[4][4][4];
  #pragma unroll
  for (int mi = 0; mi < 4; mi++)
    #pragma unroll
    for (int ni = 0; ni < 4; ni++)
      #pragma unroll
      for (int q = 0; q < 4; q++) c[mi][ni][q] = 0.f;

  const int KT = K / 16;
  issue_stage(0, 0);
  issue_stage(1, 1);
  int buf = 0;
  for (int kt = 0; kt < KT; kt++) {
    if (kt + 1 < KT) {
      asm volatile("cp.async.wait_group 1;");
    } else {
      asm volatile("cp.async.wait_group 0;");
    }
    __syncthreads();
    if (kt + 2 < KT) issue_stage(kt + 2, (kt + 2) % 3);

    const uint32_t* AHs = smu + buf * 4 * TSZP;
    const uint32_t* ALs = AHs + TSZP;
    const uint32_t* BHs = AHs + 2 * TSZP;
    const uint32_t* BLs = AHs + 3 * TSZP;

    uint32_t bH0[4], bH1[4], bL0[4], bL1[4];
    #pragma unroll
    for (int ni = 0; ni < 4; ni++) {
      int n = wn * 32 + ni * 8 + grp;
      bH0[ni] = BHs[tig * MLDP + n];
      bH1[ni] = BHs[(tig + 4) * MLDP + n];
      bL0[ni] = BLs[tig * MLDP + n];
      bL1[ni] = BLs[(tig + 4) * MLDP + n];
    }
    #pragma unroll
    for (int mi = 0; mi < 4; mi++) {
      int m = wm * 64 + mi * 16 + grp;
      uint32_t aH0 = AHs[tig * MLDP + m];
      uint32_t aH1 = AHs[tig * MLDP + m + 8];
      uint32_t aH2 = AHs[(tig + 4) * MLDP + m];
      uint32_t aH3 = AHs[(tig + 4) * MLDP + m + 8];
      uint32_t aL0 = ALs[tig * MLDP + m];
      uint32_t aL1 = ALs[tig * MLDP + m + 8];
      uint32_t aL2 = ALs[(tig + 4) * MLDP + m];
      uint32_t aL3 = ALs[(tig + 4) * MLDP + m + 8];
      #pragma unroll
      for (int ni = 0; ni < 4; ni++) {
        mma_bf16(c[mi][ni], aH0, aH1, aH2, aH3, bH0[ni], bH1[ni]);
        mma_bf16(c[mi][ni], aH0, aH1, aH2, aH3, bL0[ni], bL1[ni]);
        mma_bf16(c[mi][ni], aL0, aL1, aL2, aL3, bH0[ni], bH1[ni]);
      }
    }
    buf = (buf + 1 == 3) ? 0 : buf + 1;
  }

  // ---- epilogue ----
  const int zb = (int)blockIdx.z * zMul;
  #pragma unroll
  for (int mi = 0; mi < 4; mi++) {
    #pragma unroll
    for (int half = 0; half < 2; half++) {
      int ml = wm * 64 + mi * 16 + grp + 8 * half;
      int row = m0 + ml;
      if (EPI == 0) {
        float bm = biasM[row];
        #pragma unroll
        for (int ni = 0; ni < 4; ni++) {
          int nn = wn * 32 + ni * 8 + 2 * tig;
          float v0 = c[mi][ni][2 * half + 0] + bm;
          float v1 = c[mi][ni][2 * half + 1] + bm;
          uint32_t hw, lw;
          pack_pair(v0, v1, hw, lw);
          long o = (long)((n0 + nn) >> 1) * ldc + zb + row;
          CH[o] = hw;
          CL[o] = lw;
        }
      } else {
        float blv = Rp[4 * 128 + ml];
        float w10 = Rp[0 * 128 + ml], w11 = Rp[1 * 128 + ml];
        float w12 = Rp[2 * 128 + ml], w13 = Rp[3 * 128 + ml];
        #pragma unroll
        for (int ni = 0; ni < 4; ni++) {
          int nn = wn * 32 + ni * 8 + 2 * tig;
          float v0 = c[mi][ni][2 * half + 0]
                   + Ep[nn] + blv * Ep[128 + nn]
                   + w10 * Ep[2 * 128 + nn] + w11 * Ep[3 * 128 + nn]
                   + w12 * Ep[4 * 128 + nn] + w13 * Ep[5 * 128 + nn];
          float v1 = c[mi][ni][2 * half + 1]
                   + Ep[nn + 1] + blv * Ep[128 + nn + 1]
                   + w10 * Ep[2 * 128 + nn + 1] + w11 * Ep[3 * 128 + nn + 1]
                   + w12 * Ep[4 * 128 + nn + 1] + w13 * Ep[5 * 128 + nn + 1];
          *(float2*)&Cf[(long)row * N + n0 + nn] = make_float2(v0, v1);
        }
      }
    }
  }
}

// ---------------- host launcher ----------------
extern "C" void kernel_launch(void* const* d_in, const int* in_sizes, int n_in,
                              void* d_out, int out_size) {
  const float* x      = (const float*)d_in[0];
  const float* ln_w   = (const float*)d_in[1];
  const float* ln_b   = (const float*)d_in[2];
  const float* wq     = (const float*)d_in[3];
  const float* bq     = (const float*)d_in[4];
  const float* wk     = (const float*)d_in[5];
  const float* bk     = (const float*)d_in[6];
  const float* wv     = (const float*)d_in[7];
  const float* bv     = (const float*)d_in[8];
  const float* wo     = (const float*)d_in[9];
  const float* bo     = (const float*)d_in[10];
  const float* off1_w = (const float*)d_in[11];
  const float* off1_b = (const float*)d_in[12];
  const float* off2_w = (const float*)d_in[13];
  const float* bias1d = (const float*)d_in[14];
  const float* wq2    = (const float*)d_in[15];
  const float* bq2    = (const float*)d_in[16];
  const float* wk2    = (const float*)d_in[17];
  const float* bk2    = (const float*)d_in[18];
  const float* wv2    = (const float*)d_in[19];
  const float* bv2    = (const float*)d_in[20];
  const float* wo2    = (const float*)d_in[21];
  const float* bo2    = (const float*)d_in[22];
  const float* offc1w = (const float*)d_in[23];
  const float* offc1b = (const float*)d_in[24];
  const float* offc2w = (const float*)d_in[25];
  const float* bias2d = (const float*)d_in[26];
  const float* write_w= (const float*)d_in[27];
  const float* write_b= (const float*)d_in[28];
  const float* proj_w = (const float*)d_in[29];
  const float* proj_b = (const float*)d_in[30];
  float* out = (float*)d_out;

  float *xn, *Z, *w1, *U, *Weff, *beff, *cB;
  float *cat0, *sclq, *qcat, *cat1, *cat2, *scl2, *cat3, *Kg, *Vg;
  uint32_t *wtH, *wtL, *ytH, *ytL, *x2dH, *x2dL, *pbH, *pbL;
  cudaGetSymbolAddress((void**)&xn,    g_xn);
  cudaGetSymbolAddress((void**)&Z,     g_Z);
  cudaGetSymbolAddress((void**)&w1,    g_w1);
  cudaGetSymbolAddress((void**)&U,     g_U);
  cudaGetSymbolAddress((void**)&Weff,  g_Weff);
  cudaGetSymbolAddress((void**)&beff,  g_beff);
  cudaGetSymbolAddress((void**)&cB,    g_cB);
  cudaGetSymbolAddress((void**)&cat0,  g_cat0);
  cudaGetSymbolAddress((void**)&sclq,  g_sclq);
  cudaGetSymbolAddress((void**)&qcat,  g_qcat);
  cudaGetSymbolAddress((void**)&cat1,  g_cat1);
  cudaGetSymbolAddress((void**)&cat2,  g_cat2);
  cudaGetSymbolAddress((void**)&scl2,  g_scl2);
  cudaGetSymbolAddress((void**)&cat3,  g_cat3);
  cudaGetSymbolAddress((void**)&Kg,    g_Kg2);
  cudaGetSymbolAddress((void**)&Vg,    g_Vg2);
  cudaGetSymbolAddress((void**)&wtH,   g_wtH);
  cudaGetSymbolAddress((void**)&wtL,   g_wtL);
  cudaGetSymbolAddress((void**)&ytH,   g_ytH);
  cudaGetSymbolAddress((void**)&ytL,   g_ytL);
  cudaGetSymbolAddress((void**)&x2dH,  g_x2dH);
  cudaGetSymbolAddress((void**)&x2dL,  g_x2dL);
  cudaGetSymbolAddress((void**)&pbH,   g_pbH);
  cudaGetSymbolAddress((void**)&pbL,   g_pbL);

  // 1-2: offset-net weights (ln_z needs U)
  weff_kernel<<<3 * CG, 128>>>(off1_w, off2_w, Weff);
  u_kernel<<<DM / 8, 256>>>(wq, Weff, U);

  // 3: fused LayerNorm + Z
  ln_z_kernel<<<BSZ * SEQ / 8, 256>>>(x, ln_w, ln_b, U, xn, Z);

  // 4-5: pack constant operands
  convPair_kernel<<<(KP2 * SEQ) / 256, 256>>>(write_w, wtH, wtL, SEQ, 10);
  convPair_kernel<<<((DM / 2) * DM) / 256, 256>>>(proj_w + (long long)DM * DM, pbH, pbL, DM, 9);

  // 6: 2D patch branch (profiled slot) -> packed yt
  int patch_smem = (int)sizeof(PatchSmem);
  cudaFuncSetAttribute((const void*)patch_kernel,
                       cudaFuncAttributeMaxDynamicSharedMemorySize, patch_smem);
  patch_kernel<<<BSZ * NP, 512, patch_smem>>>(xn, ytH, ytL, offc1w, offc1b, offc2w,
                                              wq2, bq2, wk2, bk2, wv2, bv2, wo2, bo2, bias2d);

  // constants + small chain
  cb_kernel<<<1, 128>>>(off1_b, off2_w, bq, bo, Weff, beff, cB, sclq, scl2, cat0, cat1, cat2);
  w1_kernel<<<dim3(BSZ * NG, SEQ / 256), 256>>>(Z, beff, cB, w1);
  w1x_kernel<<<dim3(BSZ, 4, 4), 128>>>(xn, w1, cat0, sclq);
  kgvg_kernel<<<dim3(BSZ * NG, 4), 128>>>(xn, wk, wv, Kg, Vg);
  rowgemm2<<<dim3(80, DM / 128), 128>>>(cat0, wq, qcat, DM, DM, sclq, 0.f, bq);
  attn_kernel<<<dim3(BSZ, NH), CH>>>(qcat, Kg, Vg, bk, bv, cat1);
  rowgemm2<<<dim3(81, DM / 128), 128>>>(cat1, wo, cat2, DM, DM, nullptr, 0.f, nullptr);
  rowgemm2<<<dim3(82, DM / 128), 128>>>(cat2, proj_w, cat3, DM, DM, scl2, 0.f, proj_b);

  // write GEMM
  cudaFuncSetAttribute((const void*)mma_gemm2<0>,
                       cudaFuncAttributeMaxDynamicSharedMemorySize, G_SMEM_BYTES);
  mma_gemm2<0><<<dim3(DM / 128, SEQ / 128, BSZ), 256, G_SMEM_BYTES>>>(
      wtH, wtL, SEQ, ytH, ytL, DM, (long long)KP2 * DM, DM, P2,
      write_b, nullptr, x2dH, x2dL, BSZ * SEQ, SEQ,
      nullptr, nullptr, nullptr);

  // final GEMM
  cudaFuncSetAttribute((const void*)mma_gemm2<1>,
                       cudaFuncAttributeMaxDynamicSharedMemorySize, G_SMEM_BYTES);
  mma_gemm2<1><<<dim3(DM / 128, BSZ * SEQ / 128, 1), 256, G_SMEM_BYTES>>>(
      x2dH, x2dL, BSZ * SEQ, pbH, pbL, DM, 0, DM, DM,
      nullptr, out, nullptr, nullptr, 0, 0,
      w1, cat3, bias1d);
}

// round 13
// speedup vs baseline: 1.0587x; 1.0587x over previous
#include <cuda_runtime.h>
#include <cuda_bf16.h>
#include <math.h>
#include <stdint.h>

// ---------------- problem dims ----------------
constexpr int BSZ = 16;
constexpr int SEQ = 1024;
constexpr int DM  = 512;
constexpr int NG  = 4;
constexpr int CG  = 128;
constexpr int NH  = 8;
constexpr int CH  = 64;
constexpr int NP  = 127;
constexpr int PL  = 16;
constexpr int P2  = NP * PL;   // 2032
constexpr int KP2 = P2 / 2;    // 1016

// ---------------- scratch ----------------
__device__ float g_xn [(size_t)BSZ*SEQ*DM];
__device__ float g_Z  [(size_t)BSZ*SEQ*12];
__device__ float g_w1 [BSZ*NG*SEQ];
__device__ float g_U   [DM*12];
__device__ float g_Weff[3*CG];
__device__ float g_beff[1];
__device__ float g_cB  [12];
__device__ float g_cat0[80*DM];
__device__ float g_sclq[80];
__device__ float g_qcat[80*DM];
__device__ float g_cat1[81*DM];
__device__ float g_cat2[82*DM];
__device__ float g_scl2[82];
__device__ float g_cat3[82*DM];
__device__ float g_Kg2[BSZ*NG*DM];
__device__ float g_Vg2[BSZ*NG*DM];
__device__ uint32_t g_wtH[(size_t)KP2*SEQ];
__device__ uint32_t g_wtL[(size_t)KP2*SEQ];
__device__ uint32_t g_ytH[(size_t)BSZ*KP2*DM];
__device__ uint32_t g_ytL[(size_t)BSZ*KP2*DM];
__device__ uint32_t g_x2dH[(size_t)(DM/2)*BSZ*SEQ];
__device__ uint32_t g_x2dL[(size_t)(DM/2)*BSZ*SEQ];
__device__ uint32_t g_pbH[(DM/2)*DM];
__device__ uint32_t g_pbL[(DM/2)*DM];

__device__ __forceinline__ float warp_sum(float v) {
  #pragma unroll
  for (int o = 16; o; o >>= 1) v += __shfl_xor_sync(0xffffffffu, v, o);
  return v;
}
__device__ __forceinline__ void split_bf16(float v, uint32_t& hb, uint32_t& lb) {
  __nv_bfloat16 h = __float2bfloat16(v);
  float hf = __bfloat162float(h);
  __nv_bfloat16 l = __float2bfloat16(v - hf);
  hb = (uint32_t)__bfloat16_as_ushort(h);
  lb = (uint32_t)__bfloat16_as_ushort(l);
}
__device__ __forceinline__ void pack_pair(float v0, float v1, uint32_t& hw, uint32_t& lw) {
  uint32_t h0, l0, h1, l1;
  split_bf16(v0, h0, l0);
  split_bf16(v1, h1, l1);
  hw = h0 | (h1 << 16);
  lw = l0 | (l1 << 16);
}
__device__ __forceinline__ void mma_bf16(float* c,
    uint32_t a0, uint32_t a1, uint32_t a2, uint32_t a3,
    uint32_t b0, uint32_t b1) {
  asm volatile(
    "mma.sync.aligned.m16n8k16.row.col.f32.bf16.bf16.f32 "
    "{%0,%1,%2,%3}, {%4,%5,%6,%7}, {%8,%9}, {%0,%1,%2,%3};"
    : "+f"(c[0]), "+f"(c[1]), "+f"(c[2]), "+f"(c[3])
    : "r"(a0), "r"(a1), "r"(a2), "r"(a3), "r"(b0), "r"(b1));
}
__device__ __forceinline__ uint32_t smem_u32(const void* p) {
  uint32_t a;
  asm("{ .reg .u64 t; cvta.to.shared.u64 t, %1; cvt.u32.u64 %0, t; }" : "=r"(a) : "l"(p));
  return a;
}
__device__ __forceinline__ void cp_async16(uint32_t s, const void* g) {
  asm volatile("cp.async.cg.shared.global [%0], [%1], 16;" :: "r"(s), "l"(g));
}

// ---------------- LayerNorm ----------------
__global__ void ln_kernel(const float* __restrict__ x,
                          const float* __restrict__ lw,
                          const float* __restrict__ lb,
                          float* __restrict__ xn) {
  long row = blockIdx.x;
  const float* xr = x + row * DM;
  float* o = xn + row * DM;
  int t = threadIdx.x; // 256
  float v0 = xr[t], v1 = xr[t + 256];
  __shared__ float red[8];
  float s = warp_sum(v0 + v1);
  if ((t & 31) == 0) red[t >> 5] = s;
  __syncthreads();
  float tot = 0;
  #pragma unroll
  for (int i = 0; i < 8; i++) tot += red[i];
  float mu = tot * (1.0f / 512.0f);
  __syncthreads();
  float d0 = v0 - mu, d1 = v1 - mu;
  float sq = warp_sum(d0 * d0 + d1 * d1);
  if ((t & 31) == 0) red[t >> 5] = sq;
  __syncthreads();
  float vtot = 0;
  #pragma unroll
  for (int i = 0; i < 8; i++) vtot += red[i];
  float inv = rsqrtf(vtot * (1.0f / 512.0f) + 1e-5f);
  o[t]       = d0 * inv * lw[t]       + lb[t];
  o[t + 256] = d1 * inv * lw[t + 256] + lb[t + 256];
}

// ---------------- Weff ----------------
__global__ void weff_kernel(const float* __restrict__ off1_w,
                            const float* __restrict__ off2_w,
                            float* __restrict__ Weff) {
  int outi = blockIdx.x;
  int t = threadIdx.x; // 128
  __shared__ float red[4];
  float p = off1_w[(long)outi * CG + t] * off2_w[t];
  p = warp_sum(p);
  if ((t & 31) == 0) red[t >> 5] = p;
  __syncthreads();
  if (t == 0) Weff[outi] = red[0] + red[1] + red[2] + red[3];
}

// ---------------- constants + zero-init of accumulators ----------------
__global__ void cb_kernel(const float* __restrict__ off1_b,
                          const float* __restrict__ off2_w,
                          const float* __restrict__ bq,
                          const float* __restrict__ bo,
                          const float* __restrict__ Weff,
                          float* __restrict__ beff, float* __restrict__ cB,
                          float* __restrict__ sclq, float* __restrict__ scl2,
                          float* __restrict__ cat0,
                          float* __restrict__ cat1, float* __restrict__ cat2) {
  int t = threadIdx.x; // 128
  if (t < 12) {
    int w = t >> 2, g = t & 3;
    float s = 0.f;
    for (int c = 0; c < CG; c++) s += bq[g * CG + c] * Weff[w * CG + c];
    cB[t] = s;
  } else if (t == 12) {
    float s = 0.f;
    for (int o = 0; o < CG; o++) s += off1_b[o] * off2_w[o];
    *beff = s;
  }
  if (t < 64) sclq[t] = 0.f;
  if (t >= 64 && t < 80) sclq[t] = 1024.f;
  if (t < 82) scl2[t] = (t == 81) ? 1.f : 0.f;
  for (int j = t; j < DM; j += 128) {
    cat1[80 * DM + j] = 1.f;
    cat2[81 * DM + j] = bo[j];
  }
  for (int j = t; j < 80 * DM; j += 128) cat0[j] = 0.f;
}

// ---------------- U: warp per d ----------------
__global__ void u_kernel(const float* __restrict__ wq, const float* __restrict__ Weff,
                         float* __restrict__ U) {
  int tid = threadIdx.x; // 256
  int warp = tid >> 5, lane = tid & 31;
  int d = blockIdx.x * 8 + warp;
  float wqv[16], we[12];
  #pragma unroll
  for (int g = 0; g < 4; g++)
    #pragma unroll
    for (int k = 0; k < 4; k++)
      wqv[g * 4 + k] = wq[d * DM + g * CG + k * 32 + lane];
  #pragma unroll
  for (int w = 0; w < 3; w++)
    #pragma unroll
    for (int k = 0; k < 4; k++)
      we[w * 4 + k] = Weff[w * CG + k * 32 + lane];
  #pragma unroll
  for (int w = 0; w < 3; w++) {
    #pragma unroll
    for (int g = 0; g < 4; g++) {
      float s = 0.f;
      #pragma unroll
      for (int k = 0; k < 4; k++) s += wqv[g * 4 + k] * we[w * 4 + k];
      s = warp_sum(s);
      if (lane == 0) U[d * 12 + w * 4 + g] = s;
    }
  }
}

// ---------------- Z = xn @ U ----------------
__global__ void z_kernel(const float* __restrict__ xn, const float* __restrict__ U,
                         float* __restrict__ Z) {
  __shared__ float Us[DM * 13];
  int tid = threadIdx.x; // 256
  for (int idx = tid; idx < DM * 12; idx += 256) {
    int d = idx / 12, j = idx - d * 12;
    Us[d * 13 + j] = U[idx];
  }
  __syncthreads();
  int warp = tid >> 5, lane = tid & 31;
  long row = (long)blockIdx.x * 8 + warp;
  const float* xr = xn + row * DM;
  float acc[12];
  #pragma unroll
  for (int j = 0; j < 12; j++) acc[j] = 0.f;
  for (int i = lane; i < DM; i += 32) {
    float xv = xr[i];
    #pragma unroll
    for (int j = 0; j < 12; j++) acc[j] += xv * Us[i * 13 + j];
  }
  #pragma unroll
  for (int j = 0; j < 12; j++) acc[j] = warp_sum(acc[j]);
  if (lane == 0) {
    #pragma unroll
    for (int j = 0; j < 12; j++) Z[row * 12 + j] = acc[j];
  }
}

__global__ void w1_kernel(const float* __restrict__ Z, const float* __restrict__ beff,
                          const float* __restrict__ cB, float* __restrict__ w1) {
  int bg = blockIdx.x;
  int b = bg >> 2, g = bg & 3;
  int l = blockIdx.y * 256 + threadIdx.x;
  float s = *beff;
  #pragma unroll
  for (int w = 0; w < 3; w++) {
    int lw = l + w - 1;
    if (lw >= 0 && lw < SEQ)
      s += Z[((long)b * SEQ + lw) * 12 + w * 4 + g] + cB[w * 4 + g];
  }
  float off = tanhf(s) * 3.0f;
  float ixv = ((float)l + off) * (1.0f / 1023.0f) - 0.5f;
  w1[bg * SEQ + l] = 1.0f - fabsf(ixv);
}

// ---------------- w1x: strip-parallel, atomics ----------------
__global__ void w1x_kernel(const float* __restrict__ xn, const float* __restrict__ w1,
                           float* __restrict__ cat0, float* __restrict__ sclq) {
  int b = blockIdx.x, ec = blockIdx.y, ls = blockIdx.z;
  int e = ec * 128 + threadIdx.x;  // 128 threads
  int lbeg = ls * 256;
  __shared__ float w1s[NG][256];
  int tid = threadIdx.x;
  for (int idx = tid; idx < NG * 256; idx += 128) {
    int g = idx >> 8, l = idx & 255;
    w1s[g][l] = w1[(b * NG + g) * SEQ + lbeg + l];
  }
  __syncthreads();
  float a0 = 0, a1 = 0, a2 = 0, a3 = 0, as_ = 0;
  const float* xb = xn + ((long)b * SEQ + lbeg) * DM + e;
  for (int l = 0; l < 256; l++) {
    float xv = xb[(long)l * DM];
    a0 += xv * w1s[0][l]; a1 += xv * w1s[1][l];
    a2 += xv * w1s[2][l]; a3 += xv * w1s[3][l];
    as_ += xv;
  }
  atomicAdd(&cat0[(b * NG + 0) * DM + e], a0);
  atomicAdd(&cat0[(b * NG + 1) * DM + e], a1);
  atomicAdd(&cat0[(b * NG + 2) * DM + e], a2);
  atomicAdd(&cat0[(b * NG + 3) * DM + e], a3);
  atomicAdd(&cat0[(64 + b) * DM + e], as_);
  if (ec == 0 && tid < 4) {
    float acc = 0.f;
    for (int l = 0; l < 256; l++) acc += w1s[tid][l];
    atomicAdd(&sclq[b * NG + tid], acc);
  }
}

// ---------------- Kg/Vg ----------------
__global__ void kgvg_kernel(const float* __restrict__ xn,
                            const float* __restrict__ wk, const float* __restrict__ wv,
                            float* __restrict__ Kg, float* __restrict__ Vg) {
  int bg = blockIdx.x; int b = bg >> 2, g = bg & 3;
  int e = blockIdx.y * 128 + threadIdx.x;
  __shared__ float ms[CG];
  ms[threadIdx.x] = 0.5f * (xn[((long)b * SEQ + 511) * DM + g * CG + threadIdx.x] +
                            xn[((long)b * SEQ + 512) * DM + g * CG + threadIdx.x]);
  __syncthreads();
  float sk = 0.f, sv = 0.f;
  for (int c = 0; c < CG; c++) {
    float mv = ms[c];
    sk += mv * wk[(g * CG + c) * DM + e];
    sv += mv * wv[(g * CG + c) * DM + e];
  }
  Kg[bg * DM + e] = sk;
  Vg[bg * DM + e] = sv;
}

__global__ void rowgemm2(const float* __restrict__ A, const float* __restrict__ B,
                         float* __restrict__ C, int K, int N,
                         const float* __restrict__ scalev, float cscale,
                         const float* __restrict__ biasv) {
  int r = blockIdx.x;
  int e = blockIdx.y * 128 + threadIdx.x;
  __shared__ float Ar[1024];
  for (int idx = threadIdx.x; idx < K; idx += 128)
    Ar[idx] = A ? A[(long)r * K + idx] : 1.0f;
  __syncthreads();
  float s = 0.f;
  for (int d = 0; d < K; d++) s += Ar[d] * B[(long)d * N + e];
  if (biasv) {
    float sc = scalev ? scalev[r] : cscale;
    s += sc * biasv[e];
  }
  C[(long)r * N + e] = s;
}

__global__ void attn_kernel(const float* __restrict__ qcat,
                            const float* __restrict__ Kg, const float* __restrict__ Vg,
                            const float* __restrict__ bk, const float* __restrict__ bv,
                            float* __restrict__ cat1) {
  int b = blockIdx.x, h = blockIdx.y;
  int i = threadIdx.x; // 64
  __shared__ float Kgs[NG][CH], Vgs[NG][CH], bks[CH], bvs[CH];
  __shared__ float aa[CH][CH + 1];
  #pragma unroll
  for (int g = 0; g < NG; g++) {
    Kgs[g][i] = Kg[(b * NG + g) * DM + h * CH + i];
    Vgs[g][i] = Vg[(b * NG + g) * DM + h * CH + i];
  }
  bks[i] = bk[h * CH + i];
  bvs[i] = bv[h * CH + i];
  __syncthreads();
  float qw0 = qcat[(b * NG + 0) * DM + h * CH + i];
  float qw1 = qcat[(b * NG + 1) * DM + h * CH + i];
  float qw2 = qcat[(b * NG + 2) * DM + h * CH + i];
  float qw3 = qcat[(b * NG + 3) * DM + h * CH + i];
  float qsv = qcat[(64 + b) * DM + h * CH + i];
  const float scale = 0.044194173824159216f;
  float mx = -1e30f;
  for (int j = 0; j < CH; j++) {
    float s = (qw0 * Kgs[0][j] + qw1 * Kgs[1][j] + qw2 * Kgs[2][j] + qw3 * Kgs[3][j]
               + qsv * bks[j]) * scale;
    aa[i][j] = s;
    mx = fmaxf(mx, s);
  }
  float sm = 0.f;
  for (int j = 0; j < CH; j++) { float e = expf(aa[i][j] - mx); aa[i][j] = e; sm += e; }
  float inv = 1.0f / sm;
  float ag0 = 0, ag1 = 0, ag2 = 0, ag3 = 0, ab = 0;
  for (int j = 0; j < CH; j++) {
    float w = aa[i][j] * inv;
    ag0 += w * Vgs[0][j]; ag1 += w * Vgs[1][j];
    ag2 += w * Vgs[2][j]; ag3 += w * Vgs[3][j];
    ab  += w * bvs[j];
  }
  cat1[(b * NG + 0) * DM + h * CH + i] = ag0;
  cat1[(b * NG + 1) * DM + h * CH + i] = ag1;
  cat1[(b * NG + 2) * DM + h * CH + i] = ag2;
  cat1[(b * NG + 3) * DM + h * CH + i] = ag3;
  cat1[(64 + b) * DM + h * CH + i] = ab;
}

// ---------------- per-patch 2D deformable attention (256 threads) ---------
constexpr int PDW = DM + 4;
struct PatchSmem {
  float P[PL][PDW];
  float XS[PL][PDW];
  float sc[PL][PL + 1];
  float attnb[PL];
  float rsP[PL];
  float rsX[PL];
  float red[2][PL][PL];
};

__global__ void patch_kernel(const float* __restrict__ xn,
                             uint32_t* __restrict__ ytH, uint32_t* __restrict__ ytL,
                             const float* __restrict__ offc1w, const float* __restrict__ offc1b,
                             const float* __restrict__ offc2w,
                             const float* __restrict__ wq2, const float* __restrict__ bq2,
                             const float* __restrict__ wk2, const float* __restrict__ bk2,
                             const float* __restrict__ wv2, const float* __restrict__ bv2,
                             const float* __restrict__ wo2, const float* __restrict__ bo2,
                             const float* __restrict__ bias2d) {
  extern __shared__ char smraw[];
  PatchSmem& S = *(PatchSmem*)smraw;
  int pb = blockIdx.x;
  int b = pb / NP, p = pb % NP;
  int tid = threadIdx.x; // 256
  const float* src = xn + ((long)b * SEQ + p * 8) * DM;
  for (int idx = tid; idx < PL * DM / 4; idx += 256) {
    int i = idx >> 7, j4 = (idx & 127) * 4;
    *(float4*)&S.P[i][j4] = *(const float4*)(src + i * DM + j4);
  }
  __syncthreads();

  float WQ2 = *wq2, BQ2 = *bq2;
  float cw[9];
  #pragma unroll
  for (int t = 0; t < 9; t++) cw[t] = offc1w[t];
  float c1b = *offc1b;
  float ow0 = offc2w[0], ow1 = offc2w[1];

  for (int idx = tid; idx < PL * DM; idx += 256) {
    int i = idx >> 9, j = idx & 511;
    float h2 = c1b;
    #pragma unroll
    for (int di = -1; di <= 1; di++) {
      int ii = i + di;
      if (ii < 0 || ii > PL - 1) continue;
      #pragma unroll
      for (int dj = -1; dj <= 1; dj++) {
        int jj = j + dj;
        if (jj < 0 || jj > DM - 1) continue;
        h2 += (WQ2 * S.P[ii][jj] + BQ2) * cw[(di + 1) * 3 + (dj + 1)];
      }
    }
    float ox = tanhf(h2 * ow0) * 3.0f;
    float oy = tanhf(h2 * ow1) * 3.0f;
    float ix = ((float)j + ox) * (512.0f / 511.0f) - 0.5f;
    float iy = ((float)i + oy) * (16.0f / 15.0f) - 0.5f;
    float x0f = floorf(ix), y0f = floorf(iy);
    int x0 = (int)x0f, y0 = (int)y0f;
    float wx = ix - x0f, wy = iy - y0f;
    float acc = 0.f;
    if (x0 >= 0 && x0 < DM && y0 >= 0 && y0 < PL)                 acc += S.P[y0][x0]         * (1 - wx) * (1 - wy);
    if (x0 + 1 >= 0 && x0 + 1 < DM && y0 >= 0 && y0 < PL)         acc += S.P[y0][x0 + 1]     * wx * (1 - wy);
    if (x0 >= 0 && x0 < DM && y0 + 1 >= 0 && y0 + 1 < PL)         acc += S.P[y0 + 1][x0]     * (1 - wx) * wy;
    if (x0 + 1 >= 0 && x0 + 1 < DM && y0 + 1 >= 0 && y0 + 1 < PL) acc += S.P[y0 + 1][x0 + 1] * wx * wy;
    S.XS[i][j] = acc;
  }
  __syncthreads();

  {
    int i = tid >> 4, seg = tid & 15;
    float sp = 0.f, sx = 0.f;
    int w0 = seg * 32;
    for (int w = w0; w < w0 + 32; w++) { sp += S.P[i][w]; sx += S.XS[i][w]; }
    S.red[0][i][seg] = sp;
    S.red[1][i][seg] = sx;
  }
  __syncthreads();
  if (tid < 2 * PL) {
    int arr = tid >> 4, i = tid & 15;
    float s = 0.f;
    #pragma unroll
    for (int seg = 0; seg < 16; seg++) s += S.red[arr][i][seg];
    if (arr == 0) S.rsP[i] = s; else S.rsX[i] = s;
  }
  __syncthreads();

  {
    float WK2 = *wk2, BK2 = *bk2;
    float s1 = WQ2 * WK2, s2 = WQ2 * BK2, s3 = BQ2 * WK2, s4 = 512.0f * BQ2 * BK2;
    int i = tid >> 4, jj = tid & 15;
    const float4* pr = (const float4*)S.P[i];
    const float4* xr = (const float4*)S.XS[jj];
    float dx = 0.f, dy = 0.f, dz = 0.f, dw = 0.f;
    #pragma unroll 4
    for (int w4 = 0; w4 < 128; w4++) {
      float4 a = pr[w4], c = xr[w4];
      dx += a.x * c.x; dy += a.y * c.y; dz += a.z * c.z; dw += a.w * c.w;
    }
    float dot = (dx + dy) + (dz + dw);
    S.sc[i][jj] = s1 * dot + s2 * S.rsP[i] + s3 * S.rsX[jj] + s4;
  }
  __syncthreads();
  if (tid < PL) {
    int i = tid;
    float mx = -1e30f;
    for (int jj = 0; jj < PL; jj++) mx = fmaxf(mx, S.sc[i][jj]);
    float sm = 0.f;
    for (int jj = 0; jj < PL; jj++) { float e = expf(S.sc[i][jj] - mx); S.sc[i][jj] = e; sm += e; }
    float inv = 1.0f / sm;
    float ab = 0.f;
    for (int jj = 0; jj < PL; jj++) { S.sc[i][jj] *= inv; ab += S.sc[i][jj] * bias2d[jj]; }
    S.attnb[i] = ab;
  }
  __syncthreads();

  float WV2 = *wv2, BV2 = *bv2, WO2 = *wo2, BO2 = *bo2;
  for (int idx = tid; idx < 8 * 128; idx += 256) {
    int i2 = (idx >> 7) * 2;
    int w4 = (idx & 127) * 4;
    float4 s0 = {0, 0, 0, 0}, s1 = {0, 0, 0, 0};
    #pragma unroll
    for (int jj = 0; jj < PL; jj++) {
      float a0 = S.sc[i2][jj], a1 = S.sc[i2 + 1][jj];
      float4 xv = *(const float4*)&S.XS[jj][w4];
      s0.x += a0 * xv.x; s0.y += a0 * xv.y; s0.z += a0 * xv.z; s0.w += a0 * xv.w;
      s1.x += a1 * xv.x; s1.y += a1 * xv.y; s1.z += a1 * xv.z; s1.w += a1 * xv.w;
    }
    float c0 = BV2 + S.attnb[i2], c1 = BV2 + S.attnb[i2 + 1];
    float o0x = (WV2 * s0.x + c0) * WO2 + BO2, o1x = (WV2 * s1.x + c1) * WO2 + BO2;
    float o0y = (WV2 * s0.y + c0) * WO2 + BO2, o1y = (WV2 * s1.y + c1) * WO2 + BO2;
    float o0z = (WV2 * s0.z + c0) * WO2 + BO2, o1z = (WV2 * s1.z + c1) * WO2 + BO2;
    float o0w = (WV2 * s0.w + c0) * WO2 + BO2, o1w = (WV2 * s1.w + c1) * WO2 + BO2;
    uint4 hv, lv;
    pack_pair(o0x, o1x, hv.x, lv.x);
    pack_pair(o0y, o1y, hv.y, lv.y);
    pack_pair(o0z, o1z, hv.z, lv.z);
    pack_pair(o0w, o1w, hv.w, lv.w);
    long kp = (long)b * KP2 + p * 8 + (i2 >> 1);
    *(uint4*)&ytH[kp * DM + w4] = hv;
    *(uint4*)&ytL[kp * DM + w4] = lv;
  }
}

// ---------------- convert float [K][N] -> packed bf16-pair H/L [K/2][N] ----
__global__ void convPair_kernel(const float* __restrict__ src,
                                uint32_t* __restrict__ dH, uint32_t* __restrict__ dL,
                                int N, int logN) {
  long idx = (long)blockIdx.x * 256 + threadIdx.x;
  int n = (int)(idx & (N - 1));
  long kp = idx >> logN;
  float v0 = src[(2 * kp) * N + n];
  float v1 = src[(2 * kp + 1) * N + n];
  uint32_t hw, lw;
  pack_pair(v0, v1, hw, lw);
  dH[idx] = hw;
  dL[idx] = lw;
}

// ============================================================================
// bf16x3 mma.sync GEMM (R8-proven): 128x128 tile, 2 CTAs/SM, 3-stage cp.async.
// ============================================================================
constexpr int MLDP = 136;
constexpr int TSZP = 8 * MLDP;
constexpr int G_SMEM_WORDS = 3 * 4 * TSZP + 11 * 128;
constexpr int G_SMEM_BYTES = G_SMEM_WORDS * 4;

template<int EPI>
__global__ __launch_bounds__(256, 2)
void mma_gemm2(const uint32_t* __restrict__ AHg, const uint32_t* __restrict__ ALg, int lda,
               const uint32_t* __restrict__ BHg, const uint32_t* __restrict__ BLg, int ldb,
               long long sB, int N, int K,
               const float* __restrict__ biasM,
               float* __restrict__ Cf,
               uint32_t* __restrict__ CH, uint32_t* __restrict__ CL, int ldc, int zMul,
               const float* __restrict__ w1, const float* __restrict__ cat3,
               const float* __restrict__ bias1d) {
  extern __shared__ uint32_t smu[];
  float* Ep = (float*)(smu + 12 * TSZP);
  float* Rp = Ep + 6 * 128;

  BHg += blockIdx.z * sB;
  BLg += blockIdx.z * sB;
  const int m0 = blockIdx.y * 128, n0 = blockIdx.x * 128;
  const int tid = threadIdx.x;
  const int wid = tid >> 5, lane = tid & 31;
  const int wm = wid >> 2, wn = wid & 3;
  const int grp = lane >> 2, tig = lane & 3;
  const uint32_t smb = smem_u32(smu);

  if (EPI == 1 && tid < 128) {
    int bb = (int)(blockIdx.y >> 3);
    int n = n0 + tid;
    Ep[0 * 128 + tid] = cat3[(64 + bb) * 512 + n] + cat3[81 * 512 + n];
    Ep[1 * 128 + tid] = cat3[80 * 512 + n];
    Ep[2 * 128 + tid] = cat3[(bb * 4 + 0) * 512 + n];
    Ep[3 * 128 + tid] = cat3[(bb * 4 + 1) * 512 + n];
    Ep[4 * 128 + tid] = cat3[(bb * 4 + 2) * 512 + n];
    Ep[5 * 128 + tid] = cat3[(bb * 4 + 3) * 512 + n];
    int l = (m0 & 1023) + tid;
    Rp[0 * 128 + tid] = w1[(bb * 4 + 0) * 1024 + l];
    Rp[1 * 128 + tid] = w1[(bb * 4 + 1) * 1024 + l];
    Rp[2 * 128 + tid] = w1[(bb * 4 + 2) * 1024 + l];
    Rp[3 * 128 + tid] = w1[(bb * 4 + 3) * 1024 + l];
    Rp[4 * 128 + tid] = bias1d[l];
  }

  const int r = tid >> 5;
  const int cc = (tid & 31) * 4;
  auto issue_stage = [&](int kt, int buf) {
    long kp0 = (long)kt * 8 + r;
    uint32_t sd = smb + (uint32_t)(buf * 4 * TSZP + r * MLDP + cc) * 4;
    cp_async16(sd,                AHg + kp0 * lda + m0 + cc);
    cp_async16(sd + TSZP * 4,     ALg + kp0 * lda + m0 + cc);
    cp_async16(sd + 2 * TSZP * 4, BHg + kp0 * ldb + n0 + cc);
    cp_async16(sd + 3 * TSZP * 4, BLg + kp0 * ldb + n0 + cc);
    asm volatile("cp.async.commit_group;");
  };

  float c[4][4][4];
  #pragma unroll
  for (int mi = 0; mi < 4; mi++)
    #pragma unroll
    for (int ni = 0; ni < 4; ni++)
      #pragma unroll
      for (int q = 0; q < 4; q++) c[mi][ni][q] = 0.f;

  const int KT = K / 16;
  issue_stage(0, 0);
  issue_stage(1, 1);
  int buf = 0;
  for (int kt = 0; kt < KT; kt++) {
    if (kt + 1 < KT) {
      asm volatile("cp.async.wait_group 1;");
    } else {
      asm volatile("cp.async.wait_group 0;");
    }
    __syncthreads();
    if (kt + 2 < KT) issue_stage(kt + 2, (kt + 2) % 3);

    const uint32_t* AHs = smu + buf * 4 * TSZP;
    const uint32_t* ALs = AHs + TSZP;
    const uint32_t* BHs = AHs + 2 * TSZP;
    const uint32_t* BLs = AHs + 3 * TSZP;

    uint32_t bH0[4], bH1[4], bL0[4], bL1[4];
    #pragma unroll
    for (int ni = 0; ni < 4; ni++) {
      int n = wn * 32 + ni * 8 + grp;
      bH0[ni] = BHs[tig * MLDP + n];
      bH1[ni] = BHs[(tig + 4) * MLDP + n];
      bL0[ni] = BLs[tig * MLDP + n];
      bL1[ni] = BLs[(tig + 4) * MLDP + n];
    }
    #pragma unroll
    for (int mi = 0; mi < 4; mi++) {
      int m = wm * 64 + mi * 16 + grp;
      uint32_t aH0 = AHs[tig * MLDP + m];
      uint32_t aH1 = AHs[tig * MLDP + m + 8];
      uint32_t aH2 = AHs[(tig + 4) * MLDP + m];
      uint32_t aH3 = AHs[(tig + 4) * MLDP + m + 8];
      uint32_t aL0 = ALs[tig * MLDP + m];
      uint32_t aL1 = ALs[tig * MLDP + m + 8];
      uint32_t aL2 = ALs[(tig + 4) * MLDP + m];
      uint32_t aL3 = ALs[(tig + 4) * MLDP + m + 8];
      #pragma unroll
      for (int ni = 0; ni < 4; ni++) {
        mma_bf16(c[mi][ni], aH0, aH1, aH2, aH3, bH0[ni], bH1[ni]);
        mma_bf16(c[mi][ni], aH0, aH1, aH2, aH3, bL0[ni], bL1[ni]);
        mma_bf16(c[mi][ni], aL0, aL1, aL2, aL3, bH0[ni], bH1[ni]);
      }
    }
    buf = (buf + 1 == 3) ? 0 : buf + 1;
  }

  // ---- epilogue ----
  const int zb = (int)blockIdx.z * zMul;
  #pragma unroll
  for (int mi = 0; mi < 4; mi++) {
    #pragma unroll
    for (int half = 0; half < 2; half++) {
      int ml = wm * 64 + mi * 16 + grp + 8 * half;
      int row = m0 + ml;
      if (EPI == 0) {
        float bm = biasM[row];
        #pragma unroll
        for (int ni = 0; ni < 4; ni++) {
          int nn = wn * 32 + ni * 8 + 2 * tig;
          float v0 = c[mi][ni][2 * half + 0] + bm;
          float v1 = c[mi][ni][2 * half + 1] + bm;
          uint32_t hw, lw;
          pack_pair(v0, v1, hw, lw);
          long o = (long)((n0 + nn) >> 1) * ldc + zb + row;
          CH[o] = hw;
          CL[o] = lw;
        }
      } else {
        float blv = Rp[4 * 128 + ml];
        float w10 = Rp[0 * 128 + ml], w11 = Rp[1 * 128 + ml];
        float w12 = Rp[2 * 128 + ml], w13 = Rp[3 * 128 + ml];
        #pragma unroll
        for (int ni = 0; ni < 4; ni++) {
          int nn = wn * 32 + ni * 8 + 2 * tig;
          float v0 = c[mi][ni][2 * half + 0]
                   + Ep[nn] + blv * Ep[128 + nn]
                   + w10 * Ep[2 * 128 + nn] + w11 * Ep[3 * 128 + nn]
                   + w12 * Ep[4 * 128 + nn] + w13 * Ep[5 * 128 + nn];
          float v1 = c[mi][ni][2 * half + 1]
                   + Ep[nn + 1] + blv * Ep[128 + nn + 1]
                   + w10 * Ep[2 * 128 + nn + 1] + w11 * Ep[3 * 128 + nn + 1]
                   + w12 * Ep[4 * 128 + nn + 1] + w13 * Ep[5 * 128 + nn + 1];
          *(float2*)&Cf[(long)row * N + n0 + nn] = make_float2(v0, v1);
        }
      }
    }
  }
}

// ---------------- host launcher (R11 order) ----------------
extern "C" void kernel_launch(void* const* d_in, const int* in_sizes, int n_in,
                              void* d_out, int out_size) {
  const float* x      = (const float*)d_in[0];
  const float* ln_w   = (const float*)d_in[1];
  const float* ln_b   = (const float*)d_in[2];
  const float* wq     = (const float*)d_in[3];
  const float* bq     = (const float*)d_in[4];
  const float* wk     = (const float*)d_in[5];
  const float* bk     = (const float*)d_in[6];
  const float* wv     = (const float*)d_in[7];
  const float* bv     = (const float*)d_in[8];
  const float* wo     = (const float*)d_in[9];
  const float* bo     = (const float*)d_in[10];
  const float* off1_w = (const float*)d_in[11];
  const float* off1_b = (const float*)d_in[12];
  const float* off2_w = (const float*)d_in[13];
  const float* bias1d = (const float*)d_in[14];
  const float* wq2    = (const float*)d_in[15];
  const float* bq2    = (const float*)d_in[16];
  const float* wk2    = (const float*)d_in[17];
  const float* bk2    = (const float*)d_in[18];
  const float* wv2    = (const float*)d_in[19];
  const float* bv2    = (const float*)d_in[20];
  const float* wo2    = (const float*)d_in[21];
  const float* bo2    = (const float*)d_in[22];
  const float* offc1w = (const float*)d_in[23];
  const float* offc1b = (const float*)d_in[24];
  const float* offc2w = (const float*)d_in[25];
  const float* bias2d = (const float*)d_in[26];
  const float* write_w= (const float*)d_in[27];
  const float* write_b= (const float*)d_in[28];
  const float* proj_w = (const float*)d_in[29];
  const float* proj_b = (const float*)d_in[30];
  float* out = (float*)d_out;

  float *xn, *Z, *w1, *U, *Weff, *beff, *cB;
  float *cat0, *sclq, *qcat, *cat1, *cat2, *scl2, *cat3, *Kg, *Vg;
  uint32_t *wtH, *wtL, *ytH, *ytL, *x2dH, *x2dL, *pbH, *pbL;
  cudaGetSymbolAddress((void**)&xn,    g_xn);
  cudaGetSymbolAddress((void**)&Z,     g_Z);
  cudaGetSymbolAddress((void**)&w1,    g_w1);
  cudaGetSymbolAddress((void**)&U,     g_U);
  cudaGetSymbolAddress((void**)&Weff,  g_Weff);
  cudaGetSymbolAddress((void**)&beff,  g_beff);
  cudaGetSymbolAddress((void**)&cB,    g_cB);
  cudaGetSymbolAddress((void**)&cat0,  g_cat0);
  cudaGetSymbolAddress((void**)&sclq,  g_sclq);
  cudaGetSymbolAddress((void**)&qcat,  g_qcat);
  cudaGetSymbolAddress((void**)&cat1,  g_cat1);
  cudaGetSymbolAddress((void**)&cat2,  g_cat2);
  cudaGetSymbolAddress((void**)&scl2,  g_scl2);
  cudaGetSymbolAddress((void**)&cat3,  g_cat3);
  cudaGetSymbolAddress((void**)&Kg,    g_Kg2);
  cudaGetSymbolAddress((void**)&Vg,    g_Vg2);
  cudaGetSymbolAddress((void**)&wtH,   g_wtH);
  cudaGetSymbolAddress((void**)&wtL,   g_wtL);
  cudaGetSymbolAddress((void**)&ytH,   g_ytH);
  cudaGetSymbolAddress((void**)&ytL,   g_ytL);
  cudaGetSymbolAddress((void**)&x2dH,  g_x2dH);
  cudaGetSymbolAddress((void**)&x2dL,  g_x2dL);
  cudaGetSymbolAddress((void**)&pbH,   g_pbH);
  cudaGetSymbolAddress((void**)&pbL,   g_pbL);

  // LayerNorm
  ln_kernel<<<BSZ * SEQ, 256>>>(x, ln_w, ln_b, xn);

  // pack constant operands
  convPair_kernel<<<(KP2 * SEQ) / 256, 256>>>(write_w, wtH, wtL, SEQ, 10);
  convPair_kernel<<<((DM / 2) * DM) / 256, 256>>>(proj_w + (long long)DM * DM, pbH, pbL, DM, 9);

  // offset-net folding + constants (cb zero-inits cat0/sclq accumulators)
  weff_kernel<<<3 * CG, 128>>>(off1_w, off2_w, Weff);
  cb_kernel<<<1, 128>>>(off1_b, off2_w, bq, bo, Weff, beff, cB, sclq, scl2, cat0, cat1, cat2);
  u_kernel<<<DM / 8, 256>>>(wq, Weff, U);

  // Z, w1
  z_kernel<<<BSZ * SEQ / 8, 256>>>(xn, U, Z);
  w1_kernel<<<dim3(BSZ * NG, SEQ / 256), 256>>>(Z, beff, cB, w1);

  // reductions over L -> cat0, sclq (strip-parallel, atomics)
  w1x_kernel<<<dim3(BSZ, 4, 4), 128>>>(xn, w1, cat0, sclq);

  // Kg/Vg
  kgvg_kernel<<<dim3(BSZ * NG, 4), 128>>>(xn, wk, wv, Kg, Vg);

  // qcat = cat0 @ wq + sclq*bq
  rowgemm2<<<dim3(80, DM / 128), 128>>>(cat0, wq, qcat, DM, DM, sclq, 0.f, bq);

  // channel attention -> cat1
  attn_kernel<<<dim3(BSZ, NH), CH>>>(qcat, Kg, Vg, bk, bv, cat1);

  // cat2 = cat1 @ wo ; cat3 = cat2 @ P_top + scl2*proj_b
  rowgemm2<<<dim3(81, DM / 128), 128>>>(cat1, wo, cat2, DM, DM, nullptr, 0.f, nullptr);
  rowgemm2<<<dim3(82, DM / 128), 128>>>(cat2, proj_w, cat3, DM, DM, scl2, 0.f, proj_b);

  // 2D patch branch -> packed yt
  int patch_smem = (int)sizeof(PatchSmem);
  cudaFuncSetAttribute((const void*)patch_kernel,
                       cudaFuncAttributeMaxDynamicSharedMemorySize, patch_smem);
  patch_kernel<<<BSZ * NP, 256, patch_smem>>>(xn, ytH, ytL, offc1w, offc1b, offc2w,
                                              wq2, bq2, wk2, bk2, wv2, bv2, wo2, bo2, bias2d);

  // write GEMM
  cudaFuncSetAttribute((const void*)mma_gemm2<0>,
                       cudaFuncAttributeMaxDynamicSharedMemorySize, G_SMEM_BYTES);
  mma_gemm2<0><<<dim3(DM / 128, SEQ / 128, BSZ), 256, G_SMEM_BYTES>>>(
      wtH, wtL, SEQ, ytH, ytL, DM, (long long)KP2 * DM, DM, P2,
      write_b, nullptr, x2dH, x2dL, BSZ * SEQ, SEQ,
      nullptr, nullptr, nullptr);

  // final GEMM
  cudaFuncSetAttribute((const void*)mma_gemm2<1>,
                       cudaFuncAttributeMaxDynamicSharedMemorySize, G_SMEM_BYTES);
  mma_gemm2<1><<<dim3(DM / 128, BSZ * SEQ / 128, 1), 256, G_SMEM_BYTES>>>(
      x2dH, x2dL, BSZ * SEQ, pbH, pbL, DM, 0, DM, DM,
      nullptr, out, nullptr, nullptr, 0, 0,
      w1, cat3, bias1d);
}

// round 14
// speedup vs baseline: 1.0590x; 1.0003x over previous
#include <cuda_runtime.h>
#include <cuda_bf16.h>
#include <math.h>
#include <stdint.h>

// ---------------- problem dims ----------------
constexpr int BSZ = 16;
constexpr int SEQ = 1024;
constexpr int DM  = 512;
constexpr int NG  = 4;
constexpr int CG  = 128;
constexpr int NH  = 8;
constexpr int CH  = 64;
constexpr int NP  = 127;
constexpr int PL  = 16;
constexpr int P2  = NP * PL;   // 2032
constexpr int KP2 = P2 / 2;    // 1016

// ---------------- scratch ----------------
__device__ float g_xn [(size_t)BSZ*SEQ*DM];
__device__ float g_Z  [(size_t)BSZ*SEQ*12];
__device__ float g_w1 [BSZ*NG*SEQ];
__device__ float g_U   [DM*12];
__device__ float g_Weff[3*CG];
__device__ float g_beff[1];
__device__ float g_cB  [12];
__device__ float g_cat0[80*DM];
__device__ float g_sclq[80];
__device__ float g_qcat[80*DM];
__device__ float g_cat1[81*DM];
__device__ float g_cat2[82*DM];
__device__ float g_scl2[82];
__device__ float g_cat3[82*DM];
__device__ float g_Kg2[BSZ*NG*DM];
__device__ float g_Vg2[BSZ*NG*DM];
__device__ uint32_t g_wtH[(size_t)KP2*SEQ];
__device__ uint32_t g_wtL[(size_t)KP2*SEQ];
__device__ uint32_t g_ytH[(size_t)BSZ*KP2*DM];
__device__ uint32_t g_ytL[(size_t)BSZ*KP2*DM];
__device__ uint32_t g_x2dH[(size_t)(DM/2)*BSZ*SEQ];
__device__ uint32_t g_x2dL[(size_t)(DM/2)*BSZ*SEQ];
__device__ uint32_t g_pbH[(DM/2)*DM];
__device__ uint32_t g_pbL[(DM/2)*DM];

__device__ __forceinline__ float warp_sum(float v) {
  #pragma unroll
  for (int o = 16; o; o >>= 1) v += __shfl_xor_sync(0xffffffffu, v, o);
  return v;
}
__device__ __forceinline__ void split_bf16(float v, uint32_t& hb, uint32_t& lb) {
  __nv_bfloat16 h = __float2bfloat16(v);
  float hf = __bfloat162float(h);
  __nv_bfloat16 l = __float2bfloat16(v - hf);
  hb = (uint32_t)__bfloat16_as_ushort(h);
  lb = (uint32_t)__bfloat16_as_ushort(l);
}
__device__ __forceinline__ void pack_pair(float v0, float v1, uint32_t& hw, uint32_t& lw) {
  uint32_t h0, l0, h1, l1;
  split_bf16(v0, h0, l0);
  split_bf16(v1, h1, l1);
  hw = h0 | (h1 << 16);
  lw = l0 | (l1 << 16);
}
__device__ __forceinline__ void mma_bf16(float* c,
    uint32_t a0, uint32_t a1, uint32_t a2, uint32_t a3,
    uint32_t b0, uint32_t b1) {
  asm volatile(
    "mma.sync.aligned.m16n8k16.row.col.f32.bf16.bf16.f32 "
    "{%0,%1,%2,%3}, {%4,%5,%6,%7}, {%8,%9}, {%0,%1,%2,%3};"
    : "+f"(c[0]), "+f"(c[1]), "+f"(c[2]), "+f"(c[3])
    : "r"(a0), "r"(a1), "r"(a2), "r"(a3), "r"(b0), "r"(b1));
}
__device__ __forceinline__ uint32_t smem_u32(const void* p) {
  uint32_t a;
  asm("{ .reg .u64 t; cvta.to.shared.u64 t, %1; cvt.u32.u64 %0, t; }" : "=r"(a) : "l"(p));
  return a;
}
__device__ __forceinline__ void cp_async16(uint32_t s, const void* g) {
  asm volatile("cp.async.cg.shared.global [%0], [%1], 16;" :: "r"(s), "l"(g));
}

// ---------------- LayerNorm ----------------
__global__ void ln_kernel(const float* __restrict__ x,
                          const float* __restrict__ lw,
                          const float* __restrict__ lb,
                          float* __restrict__ xn) {
  long row = blockIdx.x;
  const float* xr = x + row * DM;
  float* o = xn + row * DM;
  int t = threadIdx.x; // 256
  float v0 = xr[t], v1 = xr[t + 256];
  __shared__ float red[8];
  float s = warp_sum(v0 + v1);
  if ((t & 31) == 0) red[t >> 5] = s;
  __syncthreads();
  float tot = 0;
  #pragma unroll
  for (int i = 0; i < 8; i++) tot += red[i];
  float mu = tot * (1.0f / 512.0f);
  __syncthreads();
  float d0 = v0 - mu, d1 = v1 - mu;
  float sq = warp_sum(d0 * d0 + d1 * d1);
  if ((t & 31) == 0) red[t >> 5] = sq;
  __syncthreads();
  float vtot = 0;
  #pragma unroll
  for (int i = 0; i < 8; i++) vtot += red[i];
  float inv = rsqrtf(vtot * (1.0f / 512.0f) + 1e-5f);
  o[t]       = d0 * inv * lw[t]       + lb[t];
  o[t + 256] = d1 * inv * lw[t + 256] + lb[t + 256];
}

// ---------------- Weff ----------------
__global__ void weff_kernel(const float* __restrict__ off1_w,
                            const float* __restrict__ off2_w,
                            float* __restrict__ Weff) {
  int outi = blockIdx.x;
  int t = threadIdx.x; // 128
  __shared__ float red[4];
  float p = off1_w[(long)outi * CG + t] * off2_w[t];
  p = warp_sum(p);
  if ((t & 31) == 0) red[t >> 5] = p;
  __syncthreads();
  if (t == 0) Weff[outi] = red[0] + red[1] + red[2] + red[3];
}

// ---------------- constants + zero-init of accumulators ----------------
__global__ void cb_kernel(const float* __restrict__ off1_b,
                          const float* __restrict__ off2_w,
                          const float* __restrict__ bq,
                          const float* __restrict__ bo,
                          const float* __restrict__ Weff,
                          float* __restrict__ beff, float* __restrict__ cB,
                          float* __restrict__ sclq, float* __restrict__ scl2,
                          float* __restrict__ cat0,
                          float* __restrict__ cat1, float* __restrict__ cat2) {
  int t = threadIdx.x; // 128
  if (t < 12) {
    int w = t >> 2, g = t & 3;
    float s = 0.f;
    for (int c = 0; c < CG; c++) s += bq[g * CG + c] * Weff[w * CG + c];
    cB[t] = s;
  } else if (t == 12) {
    float s = 0.f;
    for (int o = 0; o < CG; o++) s += off1_b[o] * off2_w[o];
    *beff = s;
  }
  if (t < 64) sclq[t] = 0.f;
  if (t >= 64 && t < 80) sclq[t] = 1024.f;
  if (t < 82) scl2[t] = (t == 81) ? 1.f : 0.f;
  for (int j = t; j < DM; j += 128) {
    cat1[80 * DM + j] = 1.f;
    cat2[81 * DM + j] = bo[j];
  }
  for (int j = t; j < 80 * DM; j += 128) cat0[j] = 0.f;
}

// ---------------- U: warp per d ----------------
__global__ void u_kernel(const float* __restrict__ wq, const float* __restrict__ Weff,
                         float* __restrict__ U) {
  int tid = threadIdx.x; // 256
  int warp = tid >> 5, lane = tid & 31;
  int d = blockIdx.x * 8 + warp;
  float wqv[16], we[12];
  #pragma unroll
  for (int g = 0; g < 4; g++)
    #pragma unroll
    for (int k = 0; k < 4; k++)
      wqv[g * 4 + k] = wq[d * DM + g * CG + k * 32 + lane];
  #pragma unroll
  for (int w = 0; w < 3; w++)
    #pragma unroll
    for (int k = 0; k < 4; k++)
      we[w * 4 + k] = Weff[w * CG + k * 32 + lane];
  #pragma unroll
  for (int w = 0; w < 3; w++) {
    #pragma unroll
    for (int g = 0; g < 4; g++) {
      float s = 0.f;
      #pragma unroll
      for (int k = 0; k < 4; k++) s += wqv[g * 4 + k] * we[w * 4 + k];
      s = warp_sum(s);
      if (lane == 0) U[d * 12 + w * 4 + g] = s;
    }
  }
}

// ---------------- Z = xn @ U ----------------
__global__ void z_kernel(const float* __restrict__ xn, const float* __restrict__ U,
                         float* __restrict__ Z) {
  __shared__ float Us[DM * 13];
  int tid = threadIdx.x; // 256
  for (int idx = tid; idx < DM * 12; idx += 256) {
    int d = idx / 12, j = idx - d * 12;
    Us[d * 13 + j] = U[idx];
  }
  __syncthreads();
  int warp = tid >> 5, lane = tid & 31;
  long row = (long)blockIdx.x * 8 + warp;
  const float* xr = xn + row * DM;
  float acc[12];
  #pragma unroll
  for (int j = 0; j < 12; j++) acc[j] = 0.f;
  for (int i = lane; i < DM; i += 32) {
    float xv = xr[i];
    #pragma unroll
    for (int j = 0; j < 12; j++) acc[j] += xv * Us[i * 13 + j];
  }
  #pragma unroll
  for (int j = 0; j < 12; j++) acc[j] = warp_sum(acc[j]);
  if (lane == 0) {
    #pragma unroll
    for (int j = 0; j < 12; j++) Z[row * 12 + j] = acc[j];
  }
}

__global__ void w1_kernel(const float* __restrict__ Z, const float* __restrict__ beff,
                          const float* __restrict__ cB, float* __restrict__ w1) {
  int bg = blockIdx.x;
  int b = bg >> 2, g = bg & 3;
  int l = blockIdx.y * 256 + threadIdx.x;
  float s = *beff;
  #pragma unroll
  for (int w = 0; w < 3; w++) {
    int lw = l + w - 1;
    if (lw >= 0 && lw < SEQ)
      s += Z[((long)b * SEQ + lw) * 12 + w * 4 + g] + cB[w * 4 + g];
  }
  float off = tanhf(s) * 3.0f;
  float ixv = ((float)l + off) * (1.0f / 1023.0f) - 0.5f;
  w1[bg * SEQ + l] = 1.0f - fabsf(ixv);
}

// ---------------- w1x: strip-parallel, atomics ----------------
__global__ void w1x_kernel(const float* __restrict__ xn, const float* __restrict__ w1,
                           float* __restrict__ cat0, float* __restrict__ sclq) {
  int b = blockIdx.x, ec = blockIdx.y, ls = blockIdx.z;
  int e = ec * 128 + threadIdx.x;  // 128 threads
  int lbeg = ls * 256;
  __shared__ float w1s[NG][256];
  int tid = threadIdx.x;
  for (int idx = tid; idx < NG * 256; idx += 128) {
    int g = idx >> 8, l = idx & 255;
    w1s[g][l] = w1[(b * NG + g) * SEQ + lbeg + l];
  }
  __syncthreads();
  float a0 = 0, a1 = 0, a2 = 0, a3 = 0, as_ = 0;
  const float* xb = xn + ((long)b * SEQ + lbeg) * DM + e;
  for (int l = 0; l < 256; l++) {
    float xv = xb[(long)l * DM];
    a0 += xv * w1s[0][l]; a1 += xv * w1s[1][l];
    a2 += xv * w1s[2][l]; a3 += xv * w1s[3][l];
    as_ += xv;
  }
  atomicAdd(&cat0[(b * NG + 0) * DM + e], a0);
  atomicAdd(&cat0[(b * NG + 1) * DM + e], a1);
  atomicAdd(&cat0[(b * NG + 2) * DM + e], a2);
  atomicAdd(&cat0[(b * NG + 3) * DM + e], a3);
  atomicAdd(&cat0[(64 + b) * DM + e], as_);
  if (ec == 0 && tid < 4) {
    float acc = 0.f;
    for (int l = 0; l < 256; l++) acc += w1s[tid][l];
    atomicAdd(&sclq[b * NG + tid], acc);
  }
}

// ---------------- Kg/Vg ----------------
__global__ void kgvg_kernel(const float* __restrict__ xn,
                            const float* __restrict__ wk, const float* __restrict__ wv,
                            float* __restrict__ Kg, float* __restrict__ Vg) {
  int bg = blockIdx.x; int b = bg >> 2, g = bg & 3;
  int e = blockIdx.y * 128 + threadIdx.x;
  __shared__ float ms[CG];
  ms[threadIdx.x] = 0.5f * (xn[((long)b * SEQ + 511) * DM + g * CG + threadIdx.x] +
                            xn[((long)b * SEQ + 512) * DM + g * CG + threadIdx.x]);
  __syncthreads();
  float sk = 0.f, sv = 0.f;
  for (int c = 0; c < CG; c++) {
    float mv = ms[c];
    sk += mv * wk[(g * CG + c) * DM + e];
    sv += mv * wv[(g * CG + c) * DM + e];
  }
  Kg[bg * DM + e] = sk;
  Vg[bg * DM + e] = sv;
}

__global__ void rowgemm2(const float* __restrict__ A, const float* __restrict__ B,
                         float* __restrict__ C, int K, int N,
                         const float* __restrict__ scalev, float cscale,
                         const float* __restrict__ biasv) {
  int r = blockIdx.x;
  int e = blockIdx.y * 128 + threadIdx.x;
  __shared__ float Ar[1024];
  for (int idx = threadIdx.x; idx < K; idx += 128)
    Ar[idx] = A ? A[(long)r * K + idx] : 1.0f;
  __syncthreads();
  float s = 0.f;
  for (int d = 0; d < K; d++) s += Ar[d] * B[(long)d * N + e];
  if (biasv) {
    float sc = scalev ? scalev[r] : cscale;
    s += sc * biasv[e];
  }
  C[(long)r * N + e] = s;
}

__global__ void attn_kernel(const float* __restrict__ qcat,
                            const float* __restrict__ Kg, const float* __restrict__ Vg,
                            const float* __restrict__ bk, const float* __restrict__ bv,
                            float* __restrict__ cat1) {
  int b = blockIdx.x, h = blockIdx.y;
  int i = threadIdx.x; // 64
  __shared__ float Kgs[NG][CH], Vgs[NG][CH], bks[CH], bvs[CH];
  __shared__ float aa[CH][CH + 1];
  #pragma unroll
  for (int g = 0; g < NG; g++) {
    Kgs[g][i] = Kg[(b * NG + g) * DM + h * CH + i];
    Vgs[g][i] = Vg[(b * NG + g) * DM + h * CH + i];
  }
  bks[i] = bk[h * CH + i];
  bvs[i] = bv[h * CH + i];
  __syncthreads();
  float qw0 = qcat[(b * NG + 0) * DM + h * CH + i];
  float qw1 = qcat[(b * NG + 1) * DM + h * CH + i];
  float qw2 = qcat[(b * NG + 2) * DM + h * CH + i];
  float qw3 = qcat[(b * NG + 3) * DM + h * CH + i];
  float qsv = qcat[(64 + b) * DM + h * CH + i];
  const float scale = 0.044194173824159216f;
  float mx = -1e30f;
  for (int j = 0; j < CH; j++) {
    float s = (qw0 * Kgs[0][j] + qw1 * Kgs[1][j] + qw2 * Kgs[2][j] + qw3 * Kgs[3][j]
               + qsv * bks[j]) * scale;
    aa[i][j] = s;
    mx = fmaxf(mx, s);
  }
  float sm = 0.f;
  for (int j = 0; j < CH; j++) { float e = expf(aa[i][j] - mx); aa[i][j] = e; sm += e; }
  float inv = 1.0f / sm;
  float ag0 = 0, ag1 = 0, ag2 = 0, ag3 = 0, ab = 0;
  for (int j = 0; j < CH; j++) {
    float w = aa[i][j] * inv;
    ag0 += w * Vgs[0][j]; ag1 += w * Vgs[1][j];
    ag2 += w * Vgs[2][j]; ag3 += w * Vgs[3][j];
    ab  += w * bvs[j];
  }
  cat1[(b * NG + 0) * DM + h * CH + i] = ag0;
  cat1[(b * NG + 1) * DM + h * CH + i] = ag1;
  cat1[(b * NG + 2) * DM + h * CH + i] = ag2;
  cat1[(b * NG + 3) * DM + h * CH + i] = ag3;
  cat1[(64 + b) * DM + h * CH + i] = ab;
}

// ---------------- per-patch 2D deformable attention ----------------
// sc phase and output phase register-tiled to cut smem traffic.
constexpr int PDW = DM + 4;
struct PatchSmem {
  float P[PL][PDW];
  float XS[PL][PDW];
  float sc[PL][PL + 1];
  float attnb[PL];
  float rsP[PL];
  float rsX[PL];
  float red[2][PL][PL];
};

__global__ void patch_kernel(const float* __restrict__ xn,
                             uint32_t* __restrict__ ytH, uint32_t* __restrict__ ytL,
                             const float* __restrict__ offc1w, const float* __restrict__ offc1b,
                             const float* __restrict__ offc2w,
                             const float* __restrict__ wq2, const float* __restrict__ bq2,
                             const float* __restrict__ wk2, const float* __restrict__ bk2,
                             const float* __restrict__ wv2, const float* __restrict__ bv2,
                             const float* __restrict__ wo2, const float* __restrict__ bo2,
                             const float* __restrict__ bias2d) {
  extern __shared__ char smraw[];
  PatchSmem& S = *(PatchSmem*)smraw;
  int pb = blockIdx.x;
  int b = pb / NP, p = pb % NP;
  int tid = threadIdx.x; // 256
  const float* src = xn + ((long)b * SEQ + p * 8) * DM;
  for (int idx = tid; idx < PL * DM / 4; idx += 256) {
    int i = idx >> 7, j4 = (idx & 127) * 4;
    *(float4*)&S.P[i][j4] = *(const float4*)(src + i * DM + j4);
  }
  __syncthreads();

  float WQ2 = *wq2, BQ2 = *bq2;
  float cw[9];
  #pragma unroll
  for (int t = 0; t < 9; t++) cw[t] = offc1w[t];
  float c1b = *offc1b;
  float ow0 = offc2w[0], ow1 = offc2w[1];

  for (int idx = tid; idx < PL * DM; idx += 256) {
    int i = idx >> 9, j = idx & 511;
    float h2 = c1b;
    #pragma unroll
    for (int di = -1; di <= 1; di++) {
      int ii = i + di;
      if (ii < 0 || ii > PL - 1) continue;
      #pragma unroll
      for (int dj = -1; dj <= 1; dj++) {
        int jj = j + dj;
        if (jj < 0 || jj > DM - 1) continue;
        h2 += (WQ2 * S.P[ii][jj] + BQ2) * cw[(di + 1) * 3 + (dj + 1)];
      }
    }
    float ox = tanhf(h2 * ow0) * 3.0f;
    float oy = tanhf(h2 * ow1) * 3.0f;
    float ix = ((float)j + ox) * (512.0f / 511.0f) - 0.5f;
    float iy = ((float)i + oy) * (16.0f / 15.0f) - 0.5f;
    float x0f = floorf(ix), y0f = floorf(iy);
    int x0 = (int)x0f, y0 = (int)y0f;
    float wx = ix - x0f, wy = iy - y0f;
    float acc = 0.f;
    if (x0 >= 0 && x0 < DM && y0 >= 0 && y0 < PL)                 acc += S.P[y0][x0]         * (1 - wx) * (1 - wy);
    if (x0 + 1 >= 0 && x0 + 1 < DM && y0 >= 0 && y0 < PL)         acc += S.P[y0][x0 + 1]     * wx * (1 - wy);
    if (x0 >= 0 && x0 < DM && y0 + 1 >= 0 && y0 + 1 < PL)         acc += S.P[y0 + 1][x0]     * (1 - wx) * wy;
    if (x0 + 1 >= 0 && x0 + 1 < DM && y0 + 1 >= 0 && y0 + 1 < PL) acc += S.P[y0 + 1][x0 + 1] * wx * wy;
    S.XS[i][j] = acc;
  }
  __syncthreads();

  // row sums (unchanged)
  {
    int i = tid >> 4, seg = tid & 15;
    float sp = 0.f, sx = 0.f;
    int w0 = seg * 32;
    for (int w = w0; w < w0 + 32; w++) { sp += S.P[i][w]; sx += S.XS[i][w]; }
    S.red[0][i][seg] = sp;
    S.red[1][i][seg] = sx;
  }
  __syncthreads();
  if (tid < 2 * PL) {
    int arr = tid >> 4, i = tid & 15;
    float s = 0.f;
    #pragma unroll
    for (int seg = 0; seg < 16; seg++) s += S.red[arr][i][seg];
    if (arr == 0) S.rsP[i] = s; else S.rsX[i] = s;
  }
  __syncthreads();

  // ---- sc phase: warp w computes rows (2w, 2w+1) x 16 jj, P in registers ----
  {
    float WK2 = *wk2, BK2 = *bk2;
    float s1 = WQ2 * WK2, s2 = WQ2 * BK2, s3 = BQ2 * WK2, s4 = 512.0f * BQ2 * BK2;
    int warp = tid >> 5, lane = tid & 31;
    int i0 = warp * 2, i1 = warp * 2 + 1;
    float p0[16], p1[16];
    #pragma unroll
    for (int k = 0; k < 16; k++) {
      p0[k] = S.P[i0][k * 32 + lane];
      p1[k] = S.P[i1][k * 32 + lane];
    }
    for (int jj = 0; jj < 16; jj++) {
      float d0 = 0.f, d1 = 0.f;
      #pragma unroll
      for (int k = 0; k < 16; k++) {
        float xv = S.XS[jj][k * 32 + lane];
        d0 += p0[k] * xv;
        d1 += p1[k] * xv;
      }
      d0 = warp_sum(d0);
      d1 = warp_sum(d1);
      if (lane == 0) {
        S.sc[i0][jj] = s1 * d0 + s2 * S.rsP[i0] + s3 * S.rsX[jj] + s4;
        S.sc[i1][jj] = s1 * d1 + s2 * S.rsP[i1] + s3 * S.rsX[jj] + s4;
      }
    }
  }
  __syncthreads();
  if (tid < PL) {
    int i = tid;
    float mx = -1e30f;
    for (int jj = 0; jj < PL; jj++) mx = fmaxf(mx, S.sc[i][jj]);
    float sm = 0.f;
    for (int jj = 0; jj < PL; jj++) { float e = expf(S.sc[i][jj] - mx); S.sc[i][jj] = e; sm += e; }
    float inv = 1.0f / sm;
    float ab = 0.f;
    for (int jj = 0; jj < PL; jj++) { S.sc[i][jj] *= inv; ab += S.sc[i][jj] * bias2d[jj]; }
    S.attnb[i] = ab;
  }
  __syncthreads();

  // ---- output phase: thread owns float2 column (w2 = 2*tid) across all 16 rows ----
  {
    float WV2 = *wv2, BV2 = *bv2, WO2 = *wo2, BO2 = *bo2;
    int w2 = tid * 2;
    float accx[PL], accy[PL];
    #pragma unroll
    for (int i = 0; i < PL; i++) { accx[i] = 0.f; accy[i] = 0.f; }
    #pragma unroll
    for (int jj = 0; jj < PL; jj++) {
      float2 xv = *(const float2*)&S.XS[jj][w2];
      #pragma unroll
      for (int i = 0; i < PL; i++) {
        float a = S.sc[i][jj];   // broadcast read
        accx[i] += a * xv.x;
        accy[i] += a * xv.y;
      }
    }
    long kpb = (long)b * KP2 + p * 8;
    #pragma unroll
    for (int i2 = 0; i2 < PL; i2 += 2) {
      float c0 = BV2 + S.attnb[i2], c1 = BV2 + S.attnb[i2 + 1];
      float o0x = (WV2 * accx[i2] + c0) * WO2 + BO2;
      float o1x = (WV2 * accx[i2 + 1] + c1) * WO2 + BO2;
      float o0y = (WV2 * accy[i2] + c0) * WO2 + BO2;
      float o1y = (WV2 * accy[i2 + 1] + c1) * WO2 + BO2;
      uint2 hv, lv;
      pack_pair(o0x, o1x, hv.x, lv.x);
      pack_pair(o0y, o1y, hv.y, lv.y);
      long kp = kpb + (i2 >> 1);
      *(uint2*)&ytH[kp * DM + w2] = hv;
      *(uint2*)&ytL[kp * DM + w2] = lv;
    }
  }
}

// ---------------- convert float [K][N] -> packed bf16-pair H/L [K/2][N] ----
__global__ void convPair_kernel(const float* __restrict__ src,
                                uint32_t* __restrict__ dH, uint32_t* __restrict__ dL,
                                int N, int logN) {
  long idx = (long)blockIdx.x * 256 + threadIdx.x;
  int n = (int)(idx & (N - 1));
  long kp = idx >> logN;
  float v0 = src[(2 * kp) * N + n];
  float v1 = src[(2 * kp + 1) * N + n];
  uint32_t hw, lw;
  pack_pair(v0, v1, hw, lw);
  dH[idx] = hw;
  dL[idx] = lw;
}

// ============================================================================
// bf16x3 mma.sync GEMM (R8-proven): 128x128 tile, 2 CTAs/SM, 3-stage cp.async.
// ============================================================================
constexpr int MLDP = 136;
constexpr int TSZP = 8 * MLDP;
constexpr int G_SMEM_WORDS = 3 * 4 * TSZP + 11 * 128;
constexpr int G_SMEM_BYTES = G_SMEM_WORDS * 4;

template<int EPI>
__global__ __launch_bounds__(256, 2)
void mma_gemm2(const uint32_t* __restrict__ AHg, const uint32_t* __restrict__ ALg, int lda,
               const uint32_t* __restrict__ BHg, const uint32_t* __restrict__ BLg, int ldb,
               long long sB, int N, int K,
               const float* __restrict__ biasM,
               float* __restrict__ Cf,
               uint32_t* __restrict__ CH, uint32_t* __restrict__ CL, int ldc, int zMul,
               const float* __restrict__ w1, const float* __restrict__ cat3,
               const float* __restrict__ bias1d) {
  extern __shared__ uint32_t smu[];
  float* Ep = (float*)(smu + 12 * TSZP);
  float* Rp = Ep + 6 * 128;

  BHg += blockIdx.z * sB;
  BLg += blockIdx.z * sB;
  const int m0 = blockIdx.y * 128, n0 = blockIdx.x * 128;
  const int tid = threadIdx.x;
  const int wid = tid >> 5, lane = tid & 31;
  const int wm = wid >> 2, wn = wid & 3;
  const int grp = lane >> 2, tig = lane & 3;
  const uint32_t smb = smem_u32(smu);

  if (EPI == 1 && tid < 128) {
    int bb = (int)(blockIdx.y >> 3);
    int n = n0 + tid;
    Ep[0 * 128 + tid] = cat3[(64 + bb) * 512 + n] + cat3[81 * 512 + n];
    Ep[1 * 128 + tid] = cat3[80 * 512 + n];
    Ep[2 * 128 + tid] = cat3[(bb * 4 + 0) * 512 + n];
    Ep[3 * 128 + tid] = cat3[(bb * 4 + 1) * 512 + n];
    Ep[4 * 128 + tid] = cat3[(bb * 4 + 2) * 512 + n];
    Ep[5 * 128 + tid] = cat3[(bb * 4 + 3) * 512 + n];
    int l = (m0 & 1023) + tid;
    Rp[0 * 128 + tid] = w1[(bb * 4 + 0) * 1024 + l];
    Rp[1 * 128 + tid] = w1[(bb * 4 + 1) * 1024 + l];
    Rp[2 * 128 + tid] = w1[(bb * 4 + 2) * 1024 + l];
    Rp[3 * 128 + tid] = w1[(bb * 4 + 3) * 1024 + l];
    Rp[4 * 128 + tid] = bias1d[l];
  }

  const int r = tid >> 5;
  const int cc = (tid & 31) * 4;
  auto issue_stage = [&](int kt, int buf) {
    long kp0 = (long)kt * 8 + r;
    uint32_t sd = smb + (uint32_t)(buf * 4 * TSZP + r * MLDP + cc) * 4;
    cp_async16(sd,                AHg + kp0 * lda + m0 + cc);
    cp_async16(sd + TSZP * 4,     ALg + kp0 * lda + m0 + cc);
    cp_async16(sd + 2 * TSZP * 4, BHg + kp0 * ldb + n0 + cc);
    cp_async16(sd + 3 * TSZP * 4, BLg + kp0 * ldb + n0 + cc);
    asm volatile("cp.async.commit_group;");
  };

  float c[4][4][4];
  #pragma unroll
  for (int mi = 0; mi < 4; mi++)
    #pragma unroll
    for (int ni = 0; ni < 4; ni++)
      #pragma unroll
      for (int q = 0; q < 4; q++) c[mi][ni][q] = 0.f;

  const int KT = K / 16;
  issue_stage(0, 0);
  issue_stage(1, 1);
  int buf = 0;
  for (int kt = 0; kt < KT; kt++) {
    if (kt + 1 < KT) {
      asm volatile("cp.async.wait_group 1;");
    } else {
      asm volatile("cp.async.wait_group 0;");
    }
    __syncthreads();
    if (kt + 2 < KT) issue_stage(kt + 2, (kt + 2) % 3);

    const uint32_t* AHs = smu + buf * 4 * TSZP;
    const uint32_t* ALs = AHs + TSZP;
    const uint32_t* BHs = AHs + 2 * TSZP;
    const uint32_t* BLs = AHs + 3 * TSZP;

    uint32_t bH0[4], bH1[4], bL0[4], bL1[4];
    #pragma unroll
    for (int ni = 0; ni < 4; ni++) {
      int n = wn * 32 + ni * 8 + grp;
      bH0[ni] = BHs[tig * MLDP + n];
      bH1[ni] = BHs[(tig + 4) * MLDP + n];
      bL0[ni] = BLs[tig * MLDP + n];
      bL1[ni] = BLs[(tig + 4) * MLDP + n];
    }
    #pragma unroll
    for (int mi = 0; mi < 4; mi++) {
      int m = wm * 64 + mi * 16 + grp;
      uint32_t aH0 = AHs[tig * MLDP + m];
      uint32_t aH1 = AHs[tig * MLDP + m + 8];
      uint32_t aH2 = AHs[(tig + 4) * MLDP + m];
      uint32_t aH3 = AHs[(tig + 4) * MLDP + m + 8];
      uint32_t aL0 = ALs[tig * MLDP + m];
      uint32_t aL1 = ALs[tig * MLDP + m + 8];
      uint32_t aL2 = ALs[(tig + 4) * MLDP + m];
      uint32_t aL3 = ALs[(tig + 4) * MLDP + m + 8];
      #pragma unroll
      for (int ni = 0; ni < 4; ni++) {
        mma_bf16(c[mi][ni], aH0, aH1, aH2, aH3, bH0[ni], bH1[ni]);
        mma_bf16(c[mi][ni], aH0, aH1, aH2, aH3, bL0[ni], bL1[ni]);
        mma_bf16(c[mi][ni], aL0, aL1, aL2, aL3, bH0[ni], bH1[ni]);
      }
    }
    buf = (buf + 1 == 3) ? 0 : buf + 1;
  }

  // ---- epilogue ----
  const int zb = (int)blockIdx.z * zMul;
  #pragma unroll
  for (int mi = 0; mi < 4; mi++) {
    #pragma unroll
    for (int half = 0; half < 2; half++) {
      int ml = wm * 64 + mi * 16 + grp + 8 * half;
      int row = m0 + ml;
      if (EPI == 0) {
        float bm = biasM[row];
        #pragma unroll
        for (int ni = 0; ni < 4; ni++) {
          int nn = wn * 32 + ni * 8 + 2 * tig;
          float v0 = c[mi][ni][2 * half + 0] + bm;
          float v1 = c[mi][ni][2 * half + 1] + bm;
          uint32_t hw, lw;
          pack_pair(v0, v1, hw, lw);
          long o = (long)((n0 + nn) >> 1) * ldc + zb + row;
          CH[o] = hw;
          CL[o] = lw;
        }
      } else {
        float blv = Rp[4 * 128 + ml];
        float w10 = Rp[0 * 128 + ml], w11 = Rp[1 * 128 + ml];
        float w12 = Rp[2 * 128 + ml], w13 = Rp[3 * 128 + ml];
        #pragma unroll
        for (int ni = 0; ni < 4; ni++) {
          int nn = wn * 32 + ni * 8 + 2 * tig;
          float v0 = c[mi][ni][2 * half + 0]
                   + Ep[nn] + blv * Ep[128 + nn]
                   + w10 * Ep[2 * 128 + nn] + w11 * Ep[3 * 128 + nn]
                   + w12 * Ep[4 * 128 + nn] + w13 * Ep[5 * 128 + nn];
          float v1 = c[mi][ni][2 * half + 1]
                   + Ep[nn + 1] + blv * Ep[128 + nn + 1]
                   + w10 * Ep[2 * 128 + nn + 1] + w11 * Ep[3 * 128 + nn + 1]
                   + w12 * Ep[4 * 128 + nn + 1] + w13 * Ep[5 * 128 + nn + 1];
          *(float2*)&Cf[(long)row * N + n0 + nn] = make_float2(v0, v1);
        }
      }
    }
  }
}

// ---------------- host launcher (R13 order) ----------------
extern "C" void kernel_launch(void* const* d_in, const int* in_sizes, int n_in,
                              void* d_out, int out_size) {
  const float* x      = (const float*)d_in[0];
  const float* ln_w   = (const float*)d_in[1];
  const float* ln_b   = (const float*)d_in[2];
  const float* wq     = (const float*)d_in[3];
  const float* bq     = (const float*)d_in[4];
  const float* wk     = (const float*)d_in[5];
  const float* bk     = (const float*)d_in[6];
  const float* wv     = (const float*)d_in[7];
  const float* bv     = (const float*)d_in[8];
  const float* wo     = (const float*)d_in[9];
  const float* bo     = (const float*)d_in[10];
  const float* off1_w = (const float*)d_in[11];
  const float* off1_b = (const float*)d_in[12];
  const float* off2_w = (const float*)d_in[13];
  const float* bias1d = (const float*)d_in[14];
  const float* wq2    = (const float*)d_in[15];
  const float* bq2    = (const float*)d_in[16];
  const float* wk2    = (const float*)d_in[17];
  const float* bk2    = (const float*)d_in[18];
  const float* wv2    = (const float*)d_in[19];
  const float* bv2    = (const float*)d_in[20];
  const float* wo2    = (const float*)d_in[21];
  const float* bo2    = (const float*)d_in[22];
  const float* offc1w = (const float*)d_in[23];
  const float* offc1b = (const float*)d_in[24];
  const float* offc2w = (const float*)d_in[25];
  const float* bias2d = (const float*)d_in[26];
  const float* write_w= (const float*)d_in[27];
  const float* write_b= (const float*)d_in[28];
  const float* proj_w = (const float*)d_in[29];
  const float* proj_b = (const float*)d_in[30];
  float* out = (float*)d_out;

  float *xn, *Z, *w1, *U, *Weff, *beff, *cB;
  float *cat0, *sclq, *qcat, *cat1, *cat2, *scl2, *cat3, *Kg, *Vg;
  uint32_t *wtH, *wtL, *ytH, *ytL, *x2dH, *x2dL, *pbH, *pbL;
  cudaGetSymbolAddress((void**)&xn,    g_xn);
  cudaGetSymbolAddress((void**)&Z,     g_Z);
  cudaGetSymbolAddress((void**)&w1,    g_w1);
  cudaGetSymbolAddress((void**)&U,     g_U);
  cudaGetSymbolAddress((void**)&Weff,  g_Weff);
  cudaGetSymbolAddress((void**)&beff,  g_beff);
  cudaGetSymbolAddress((void**)&cB,    g_cB);
  cudaGetSymbolAddress((void**)&cat0,  g_cat0);
  cudaGetSymbolAddress((void**)&sclq,  g_sclq);
  cudaGetSymbolAddress((void**)&qcat,  g_qcat);
  cudaGetSymbolAddress((void**)&cat1,  g_cat1);
  cudaGetSymbolAddress((void**)&cat2,  g_cat2);
  cudaGetSymbolAddress((void**)&scl2,  g_scl2);
  cudaGetSymbolAddress((void**)&cat3,  g_cat3);
  cudaGetSymbolAddress((void**)&Kg,    g_Kg2);
  cudaGetSymbolAddress((void**)&Vg,    g_Vg2);
  cudaGetSymbolAddress((void**)&wtH,   g_wtH);
  cudaGetSymbolAddress((void**)&wtL,   g_wtL);
  cudaGetSymbolAddress((void**)&ytH,   g_ytH);
  cudaGetSymbolAddress((void**)&ytL,   g_ytL);
  cudaGetSymbolAddress((void**)&x2dH,  g_x2dH);
  cudaGetSymbolAddress((void**)&x2dL,  g_x2dL);
  cudaGetSymbolAddress((void**)&pbH,   g_pbH);
  cudaGetSymbolAddress((void**)&pbL,   g_pbL);

  // LayerNorm
  ln_kernel<<<BSZ * SEQ, 256>>>(x, ln_w, ln_b, xn);

  // pack constant operands
  convPair_kernel<<<(KP2 * SEQ) / 256, 256>>>(write_w, wtH, wtL, SEQ, 10);
  convPair_kernel<<<((DM / 2) * DM) / 256, 256>>>(proj_w + (long long)DM * DM, pbH, pbL, DM, 9);

  // offset-net folding + constants
  weff_kernel<<<3 * CG, 128>>>(off1_w, off2_w, Weff);
  cb_kernel<<<1, 128>>>(off1_b, off2_w, bq, bo, Weff, beff, cB, sclq, scl2, cat0, cat1, cat2);
  u_kernel<<<DM / 8, 256>>>(wq, Weff, U);

  // Z, w1
  z_kernel<<<BSZ * SEQ / 8, 256>>>(xn, U, Z);
  w1_kernel<<<dim3(BSZ * NG, SEQ / 256), 256>>>(Z, beff, cB, w1);

  // reductions over L -> cat0, sclq
  w1x_kernel<<<dim3(BSZ, 4, 4), 128>>>(xn, w1, cat0, sclq);

  // Kg/Vg
  kgvg_kernel<<<dim3(BSZ * NG, 4), 128>>>(xn, wk, wv, Kg, Vg);

  // qcat = cat0 @ wq + sclq*bq
  rowgemm2<<<dim3(80, DM / 128), 128>>>(cat0, wq, qcat, DM, DM, sclq, 0.f, bq);

  // channel attention -> cat1
  attn_kernel<<<dim3(BSZ, NH), CH>>>(qcat, Kg, Vg, bk, bv, cat1);

  // cat2 = cat1 @ wo ; cat3 = cat2 @ P_top + scl2*proj_b
  rowgemm2<<<dim3(81, DM / 128), 128>>>(cat1, wo, cat2, DM, DM, nullptr, 0.f, nullptr);
  rowgemm2<<<dim3(82, DM / 128), 128>>>(cat2, proj_w, cat3, DM, DM, scl2, 0.f, proj_b);

  // 2D patch branch -> packed yt
  int patch_smem = (int)sizeof(PatchSmem);
  cudaFuncSetAttribute((const void*)patch_kernel,
                       cudaFuncAttributeMaxDynamicSharedMemorySize, patch_smem);
  patch_kernel<<<BSZ * NP, 256, patch_smem>>>(xn, ytH, ytL, offc1w, offc1b, offc2w,
                                              wq2, bq2, wk2, bk2, wv2, bv2, wo2, bo2, bias2d);

  // write GEMM
  cudaFuncSetAttribute((const void*)mma_gemm2<0>,
                       cudaFuncAttributeMaxDynamicSharedMemorySize, G_SMEM_BYTES);
  mma_gemm2<0><<<dim3(DM / 128, SEQ / 128, BSZ), 256, G_SMEM_BYTES>>>(
      wtH, wtL, SEQ, ytH, ytL, DM, (long long)KP2 * DM, DM, P2,
      write_b, nullptr, x2dH, x2dL, BSZ * SEQ, SEQ,
      nullptr, nullptr, nullptr);

  // final GEMM
  cudaFuncSetAttribute((const void*)mma_gemm2<1>,
                       cudaFuncAttributeMaxDynamicSharedMemorySize, G_SMEM_BYTES);
  mma_gemm2<1><<<dim3(DM / 128, BSZ * SEQ / 128, 1), 256, G_SMEM_BYTES>>>(
      x2dH, x2dL, BSZ * SEQ, pbH, pbL, DM, 0, DM, DM,
      nullptr, out, nullptr, nullptr, 0, 0,
      w1, cat3, bias1d);
}